// round 13
// baseline (speedup 1.0000x reference)
#include <cuda_runtime.h>
#include <cuda_bf16.h>

// ---------------------------------------------------------------------------
// Problem constants
// ---------------------------------------------------------------------------
#define B_   64
#define T_   50
#define E_   1024
#define H_   1024
#define NI_  32000
#define KK_  4
#define WW_  32
#define NN_  10
#define LOUT_ 993           // H - W + 1
#define M_   (B_ * T_)      // 3200 rows
#define F_   (NN_ + 2 * H_) // 2058 features into final linear
#define FPAD_ 2064          // F_ padded up to multiple of 16

// ---------------------------------------------------------------------------
// Device scratch (static, no runtime allocation)
// ---------------------------------------------------------------------------
__device__ float g_XUI[M_ * 2 * E_];          // [u | it] gathered, 3200 x 2048
__device__ float g_attpre[M_ * E_];           // 3200 x 1024
__device__ float g_WA[E_ * 4096];             // [Wh | W_hh^T], 1024 x 4096
__device__ float g_WIT[2 * E_ * 3 * H_];      // W_ih^T, 2048 x 3072
__device__ float g_h[B_ * H_];                // current hidden state
__device__ float g_gh[B_ * 3 * H_];           // h @ W_hh^T + b_hh
__device__ float g_x[B_ * 2 * E_];            // [att*u, (1-att)*it]
__device__ float g_gi[B_ * 3 * H_];           // x @ W_ih^T + b_ih
__device__ float g_buf[KK_ * B_ * H_];        // ring buffer of last K hidden states
__device__ float g_ful[M_ * FPAD_];           // concat(v, h, l) per (b,t), padded

// ---------------------------------------------------------------------------
// Init: zero h, ring buffer, and the pad columns of ful
// ---------------------------------------------------------------------------
__global__ void init_kernel() {
    const int n1 = B_ * H_;
    const int n2 = KK_ * B_ * H_;
    const int n3 = M_ * (FPAD_ - F_);
    const int tot = n1 + n2 + n3;
    for (int i = blockIdx.x * blockDim.x + threadIdx.x; i < tot;
         i += gridDim.x * blockDim.x) {
        if (i < n1)           g_h[i] = 0.f;
        else if (i < n1 + n2) g_buf[i - n1] = 0.f;
        else {
            int k = i - n1 - n2;
            int row = k / (FPAD_ - F_);
            int c = k % (FPAD_ - F_);
            g_ful[row * FPAD_ + F_ + c] = 0.f;
        }
    }
}

// ---------------------------------------------------------------------------
// Prep: build WA = [Wh | W_hh^T] (1024x4096) and WIT = W_ih^T (2048x3072)
// ---------------------------------------------------------------------------
__global__ void prep_kernel(const float* __restrict__ att_W,
                            const float* __restrict__ W_hh,
                            const float* __restrict__ W_ih) {
    const int tot1 = E_ * 4096;
    const int tot2 = 2 * E_ * 3 * H_;
    for (int i = blockIdx.x * blockDim.x + threadIdx.x; i < tot1 + tot2;
         i += gridDim.x * blockDim.x) {
        if (i < tot1) {
            int e = i >> 12;       // / 4096
            int f = i & 4095;
            g_WA[i] = (f < H_) ? att_W[(2 * E_ + e) * E_ + f]
                               : W_hh[(f - H_) * H_ + e];
        } else {
            int k = i - tot1;
            int e = k / (3 * H_);
            int j = k % (3 * H_);
            g_WIT[k] = W_ih[j * (2 * E_) + e];
        }
    }
}

// ---------------------------------------------------------------------------
// Gather: XUI[bt] = [user_emb[uv[bt]], item_emb[iv[bt]]]
// ---------------------------------------------------------------------------
__global__ void gather_kernel(const int* __restrict__ uv,
                              const int* __restrict__ iv,
                              const float* __restrict__ ue,
                              const float* __restrict__ ie) {
    const int tot = M_ * E_;
    for (int i = blockIdx.x * blockDim.x + threadIdx.x; i < tot;
         i += gridDim.x * blockDim.x) {
        int bt = i >> 10;
        int e = i & 1023;
        g_XUI[bt * 2048 + e]        = ue[(size_t)uv[bt] * E_ + e];
        g_XUI[bt * 2048 + 1024 + e] = ie[(size_t)iv[bt] * E_ + e];
    }
}

// ---------------------------------------------------------------------------
// Big GEMM: C = A @ B + bias(col). 128x128 tile, BK=16, 8x8 per thread.
// MODE 0: attpre = XUI(3200x2048) @ Batt(2048x1024), C -> g_attpre
// MODE 1: logits = ful(3200x2058 pad 2064) @ lin_W(2058x32000), C -> arg
// ---------------------------------------------------------------------------
template <int MODE>
__global__ __launch_bounds__(256)
void big_gemm_kernel(const float* __restrict__ Bm,
                     const float* __restrict__ bias,
                     float* __restrict__ Carg) {
    constexpr int KD  = (MODE == 0) ? 2048 : 2058;
    constexpr int LDA = (MODE == 0) ? 2048 : FPAD_;
    constexpr int LDB = (MODE == 0) ? 1024 : NI_;
    constexpr int LDC = (MODE == 0) ? 1024 : NI_;
    const float* A = (MODE == 0) ? g_XUI : g_ful;
    float* C = (MODE == 0) ? g_attpre : Carg;

    __shared__ float As[16][128];
    __shared__ float Bs[16][128];

    const int tid = threadIdx.x;
    const int m0 = blockIdx.y * 128;
    const int n0 = blockIdx.x * 128;
    const int tx = tid & 15;
    const int ty = tid >> 4;

    float acc[8][8];
#pragma unroll
    for (int i = 0; i < 8; i++)
#pragma unroll
        for (int j = 0; j < 8; j++) acc[i][j] = 0.f;

    const int nk = (KD + 15) / 16;
    for (int kt = 0; kt < nk; kt++) {
        const int kb = kt * 16;
        // A tile: 128 rows x 16 cols -> 512 float4, 2 per thread
#pragma unroll
        for (int i = 0; i < 2; i++) {
            int idx = tid + i * 256;
            int r = idx >> 2;
            int c4 = (idx & 3) * 4;
            float4 v;
            if (kb + c4 + 3 < KD) {
                v = *reinterpret_cast<const float4*>(&A[(size_t)(m0 + r) * LDA + kb + c4]);
            } else {
                v.x = (kb + c4 + 0 < KD) ? A[(size_t)(m0 + r) * LDA + kb + c4 + 0] : 0.f;
                v.y = (kb + c4 + 1 < KD) ? A[(size_t)(m0 + r) * LDA + kb + c4 + 1] : 0.f;
                v.z = (kb + c4 + 2 < KD) ? A[(size_t)(m0 + r) * LDA + kb + c4 + 2] : 0.f;
                v.w = 0.f;
            }
            As[c4 + 0][r] = v.x; As[c4 + 1][r] = v.y;
            As[c4 + 2][r] = v.z; As[c4 + 3][r] = v.w;
        }
        // B tile: 16 rows x 128 cols -> 512 float4, 2 per thread
#pragma unroll
        for (int i = 0; i < 2; i++) {
            int idx = tid + i * 256;
            int r = idx >> 5;
            int c4 = (idx & 31) * 4;
            float4 v = make_float4(0.f, 0.f, 0.f, 0.f);
            if (kb + r < KD)
                v = *reinterpret_cast<const float4*>(&Bm[(size_t)(kb + r) * LDB + n0 + c4]);
            *reinterpret_cast<float4*>(&Bs[r][c4]) = v;
        }
        __syncthreads();
#pragma unroll
        for (int k = 0; k < 16; k++) {
            float ra[8], rb[8];
            *reinterpret_cast<float4*>(ra)     = *reinterpret_cast<const float4*>(&As[k][ty * 8]);
            *reinterpret_cast<float4*>(ra + 4) = *reinterpret_cast<const float4*>(&As[k][ty * 8 + 4]);
            *reinterpret_cast<float4*>(rb)     = *reinterpret_cast<const float4*>(&Bs[k][tx * 8]);
            *reinterpret_cast<float4*>(rb + 4) = *reinterpret_cast<const float4*>(&Bs[k][tx * 8 + 4]);
#pragma unroll
            for (int i = 0; i < 8; i++)
#pragma unroll
                for (int j = 0; j < 8; j++) acc[i][j] += ra[i] * rb[j];
        }
        __syncthreads();
    }

#pragma unroll
    for (int i = 0; i < 8; i++) {
        int row = m0 + ty * 8 + i;
#pragma unroll
        for (int j = 0; j < 8; j += 4) {
            int col = n0 + tx * 8 + j;
            float4 v;
            v.x = acc[i][j + 0] + bias[col + 0];
            v.y = acc[i][j + 1] + bias[col + 1];
            v.z = acc[i][j + 2] + bias[col + 2];
            v.w = acc[i][j + 3] + bias[col + 3];
            *reinterpret_cast<float4*>(&C[(size_t)row * LDC + col]) = v;
        }
    }
}

// ---------------------------------------------------------------------------
// Small-M GEMM (M=64) for the scan, 64x32 tile, BK=32, 4x2 per thread.
// MODE 0 (phase1): C = h @ WA (K=1024, N=4096). Epilogue:
//   cols <1024: att = sigmoid(attpre + c); g_x = [att*u, (1-att)*it]
//   cols >=1024: g_gh = c + b_hh
// MODE 1 (phase2): C = x @ WIT (K=2048, N=3072). Epilogue: g_gi = c + b_ih
// ---------------------------------------------------------------------------
template <int MODE>
__global__ __launch_bounds__(256)
void small_gemm_kernel(int t, const float* __restrict__ bias) {
    constexpr int KD  = (MODE == 0) ? 1024 : 2048;
    constexpr int LDB = (MODE == 0) ? 4096 : 3072;
    const float* A = (MODE == 0) ? g_h : g_x;
    const float* Bm = (MODE == 0) ? g_WA : g_WIT;

    __shared__ float As[32][64];
    __shared__ float Bs[32][32];

    const int tid = threadIdx.x;
    const int n0 = blockIdx.x * 32;
    const int tx = tid & 15;
    const int ty = tid >> 4;

    float acc[4][2] = {{0.f, 0.f}, {0.f, 0.f}, {0.f, 0.f}, {0.f, 0.f}};

    for (int kb = 0; kb < KD; kb += 32) {
        // A tile 64x32: 512 float4, 2 per thread
#pragma unroll
        for (int i = 0; i < 2; i++) {
            int idx = tid + i * 256;
            int r = idx >> 3;
            int c4 = (idx & 7) * 4;
            float4 v = *reinterpret_cast<const float4*>(&A[r * KD + kb + c4]);
            As[c4 + 0][r] = v.x; As[c4 + 1][r] = v.y;
            As[c4 + 2][r] = v.z; As[c4 + 3][r] = v.w;
        }
        // B tile 32x32: 256 float4, 1 per thread
        {
            int r = tid >> 3;
            int c4 = (tid & 7) * 4;
            *reinterpret_cast<float4*>(&Bs[r][c4]) =
                *reinterpret_cast<const float4*>(&Bm[(kb + r) * LDB + n0 + c4]);
        }
        __syncthreads();
#pragma unroll
        for (int k = 0; k < 32; k++) {
            float4 a = *reinterpret_cast<const float4*>(&As[k][ty * 4]);
            float2 bv = *reinterpret_cast<const float2*>(&Bs[k][tx * 2]);
            acc[0][0] += a.x * bv.x; acc[0][1] += a.x * bv.y;
            acc[1][0] += a.y * bv.x; acc[1][1] += a.y * bv.y;
            acc[2][0] += a.z * bv.x; acc[2][1] += a.z * bv.y;
            acc[3][0] += a.w * bv.x; acc[3][1] += a.w * bv.y;
        }
        __syncthreads();
    }

#pragma unroll
    for (int i = 0; i < 4; i++) {
        int b = ty * 4 + i;
#pragma unroll
        for (int j = 0; j < 2; j++) {
            int f = n0 + tx * 2 + j;
            float c = acc[i][j];
            if (MODE == 0) {
                if (f < 1024) {
                    int row = b * T_ + t;
                    float a = 1.f / (1.f + __expf(-(g_attpre[row * E_ + f] + c)));
                    g_x[b * 2048 + f]        = a * g_XUI[row * 2048 + f];
                    g_x[b * 2048 + 1024 + f] = (1.f - a) * g_XUI[row * 2048 + 1024 + f];
                } else {
                    int j2 = f - 1024;
                    g_gh[b * 3072 + j2] = c + bias[j2];
                }
            } else {
                g_gi[b * 3072 + f] = c + bias[f];
            }
        }
    }
}

// ---------------------------------------------------------------------------
// GRU update + sliding-window cov (v) + vertical cov (q, l) + write ful row.
// One block per batch element.
// ---------------------------------------------------------------------------
__global__ __launch_bounds__(256)
void gru_step_kernel(int t,
                     const float* __restrict__ hcov_W,
                     const float* __restrict__ hcov_b,
                     const float* __restrict__ vcov_W,
                     const float* __restrict__ vcov_b) {
    const int b = blockIdx.x;
    const int tid = threadIdx.x;
    __shared__ float hnew[H_];
    __shared__ float cs[WW_];
    __shared__ float rbuf[8];

    const float vw0 = vcov_W[0], vw1 = vcov_W[1], vw2 = vcov_W[2], vw3 = vcov_W[3];
    const float vb = vcov_b[0];
    const int row = b * T_ + t;
    const int slot = t & 3;

    for (int j = tid; j < H_; j += 256) {
        float hold = g_h[b * H_ + j];
        float gir = g_gi[b * 3072 + j];
        float giz = g_gi[b * 3072 + 1024 + j];
        float gin = g_gi[b * 3072 + 2048 + j];
        float ghr = g_gh[b * 3072 + j];
        float ghz = g_gh[b * 3072 + 1024 + j];
        float ghn = g_gh[b * 3072 + 2048 + j];
        float r = 1.f / (1.f + __expf(-(gir + ghr)));
        float z = 1.f / (1.f + __expf(-(giz + ghz)));
        float n = tanhf(gin + r * ghn);
        float hn = (1.f - z) * n + z * hold;
        hnew[j] = hn;
        g_h[b * H_ + j] = hn;
        g_buf[slot * (B_ * H_) + b * H_ + j] = hn;
        float l = 0.f;
        if (t >= KK_ - 1) {
            float q = vw0 * g_buf[((t + 1) & 3) * (B_ * H_) + b * H_ + j]
                    + vw1 * g_buf[((t + 2) & 3) * (B_ * H_) + b * H_ + j]
                    + vw2 * g_buf[((t + 3) & 3) * (B_ * H_) + b * H_ + j]
                    + vw3 * hn + vb;
            l = hn * q;
        }
        g_ful[row * FPAD_ + NN_ + j] = hn;
        g_ful[row * FPAD_ + NN_ + H_ + j] = l;
    }
    __syncthreads();

    // sum of hnew[0 .. Lout-1] (993 elements)
    float s = 0.f;
    for (int j = tid; j < LOUT_; j += 256) s += hnew[j];
#pragma unroll
    for (int o = 16; o > 0; o >>= 1) s += __shfl_down_sync(0xffffffffu, s, o);
    if ((tid & 31) == 0) rbuf[tid >> 5] = s;
    __syncthreads();
    if (tid == 0) {
        float S = 0.f;
#pragma unroll
        for (int w = 0; w < 8; w++) S += rbuf[w];
        cs[0] = S;
        for (int j = 1; j < WW_; j++)
            cs[j] = cs[j - 1] - hnew[j - 1] + hnew[LOUT_ - 1 + j];
    }
    __syncthreads();
    if (tid < NN_) {
        float v = hcov_b[tid] * (float)LOUT_;
#pragma unroll
        for (int jj = 0; jj < WW_; jj++) v += hcov_W[tid * WW_ + jj] * cs[jj];
        g_ful[row * FPAD_ + tid] = v;
    }
}

// ---------------------------------------------------------------------------
// In-place log-softmax over NI columns, one block per row.
// ---------------------------------------------------------------------------
__global__ __launch_bounds__(512)
void logsoftmax_kernel(float* __restrict__ out) {
    const int row = blockIdx.x;
    float* p = out + (size_t)row * NI_;
    const int tid = threadIdx.x;

    float m = -1e30f, s = 0.f;
    for (int c = tid; c < NI_; c += 512) {
        float v = p[c];
        if (v > m) { s = s * __expf(m - v) + 1.f; m = v; }
        else        s += __expf(v - m);
    }
#pragma unroll
    for (int o = 16; o > 0; o >>= 1) {
        float m2 = __shfl_down_sync(0xffffffffu, m, o);
        float s2 = __shfl_down_sync(0xffffffffu, s, o);
        float M = fmaxf(m, m2);
        s = s * __expf(m - M) + s2 * __expf(m2 - M);
        m = M;
    }
    __shared__ float sm[16], ss[16];
    __shared__ float off;
    if ((tid & 31) == 0) { sm[tid >> 5] = m; ss[tid >> 5] = s; }
    __syncthreads();
    if (tid == 0) {
        float M = sm[0], S = ss[0];
        for (int w = 1; w < 16; w++) {
            float m2 = sm[w], s2 = ss[w];
            float MM = fmaxf(M, m2);
            S = S * __expf(M - MM) + s2 * __expf(m2 - MM);
            M = MM;
        }
        off = M + logf(S);
    }
    __syncthreads();
    float o2 = off;
    for (int c = tid; c < NI_; c += 512) p[c] -= o2;
}

// ---------------------------------------------------------------------------
// Launch
// ---------------------------------------------------------------------------
extern "C" void kernel_launch(void* const* d_in, const int* in_sizes, int n_in,
                              void* d_out, int out_size) {
    (void)in_sizes; (void)n_in; (void)out_size;
    const int*   uv       = (const int*)d_in[0];
    const int*   iv       = (const int*)d_in[1];
    const float* user_emb = (const float*)d_in[2];
    const float* item_emb = (const float*)d_in[3];
    const float* att_W    = (const float*)d_in[4];
    const float* att_b    = (const float*)d_in[5];
    const float* W_ih     = (const float*)d_in[6];
    const float* b_ih     = (const float*)d_in[7];
    const float* W_hh     = (const float*)d_in[8];
    const float* b_hh     = (const float*)d_in[9];
    const float* hcov_W   = (const float*)d_in[10];
    const float* hcov_b   = (const float*)d_in[11];
    const float* vcov_W   = (const float*)d_in[12];
    const float* vcov_b   = (const float*)d_in[13];
    const float* lin_W    = (const float*)d_in[14];
    const float* lin_b    = (const float*)d_in[15];
    float* out = (float*)d_out;

    init_kernel<<<256, 256>>>();
    prep_kernel<<<2048, 256>>>(att_W, W_hh, W_ih);
    gather_kernel<<<2048, 256>>>(uv, iv, user_emb, item_emb);

    {   // att_pre = XUI @ att_W[:2048] + att_b
        dim3 grid(E_ / 128, M_ / 128);
        big_gemm_kernel<0><<<grid, 256>>>(att_W, att_b, nullptr);
    }

    for (int t = 0; t < T_; t++) {
        small_gemm_kernel<0><<<4096 / 32, 256>>>(t, b_hh);   // h@[Wh|W_hh^T], att, x
        small_gemm_kernel<1><<<3072 / 32, 256>>>(t, b_ih);   // gi = x@W_ih^T
        gru_step_kernel<<<B_, 256>>>(t, hcov_W, hcov_b, vcov_W, vcov_b);
    }

    {   // logits = ful @ lin_W + lin_b  -> d_out
        dim3 grid(NI_ / 128, M_ / 128);
        big_gemm_kernel<1><<<grid, 256>>>(lin_W, lin_b, out);
    }

    logsoftmax_kernel<<<M_, 512>>>(out);
}

// round 14
// speedup vs baseline: 2.1541x; 2.1541x over previous
#include <cuda_runtime.h>
#include <cuda_bf16.h>
#include <cstdint>

// ---------------------------------------------------------------------------
// Problem constants
// ---------------------------------------------------------------------------
#define B_   64
#define T_   50
#define E_   1024
#define H_   1024
#define NI_  32000
#define KK_  4
#define WW_  32
#define NN_  10
#define LOUT_ 993           // H - W + 1
#define M_   (B_ * T_)      // 3200 rows
#define F_   (NN_ + 2 * H_) // 2058 features into final linear
#define FPK_ 2080           // F_ padded to multiple of 32 (bf16 A stride)

// ---------------------------------------------------------------------------
// Device scratch (static, no runtime allocation)
// ---------------------------------------------------------------------------
__device__ __nv_bfloat16 g_XUIb[M_ * 2048];      // gathered [u|it] in bf16
__device__ float g_attpre[M_ * E_];              // 3200 x 1024 fp32
__device__ float g_WA[E_ * 4096];                // [Wh | W_hh^T]
__device__ float g_WIT[2 * E_ * 3 * H_];         // W_ih^T
__device__ float g_h[B_ * H_];
__device__ float g_gh[B_ * 3 * H_];
__device__ float g_x[B_ * 2 * E_];
__device__ float g_gi[B_ * 3 * H_];
__device__ float g_buf[KK_ * B_ * H_];
__device__ __nv_bfloat16 g_fulb[M_ * FPK_];      // concat(v,h,l) in bf16, padded
__device__ __nv_bfloat16 g_linWb[F_ * NI_];      // lin_W bf16
__device__ __nv_bfloat16 g_attWb[2048 * 1024];   // att_W[:2048] bf16

// ---------------------------------------------------------------------------
// Helpers
// ---------------------------------------------------------------------------
__device__ __forceinline__ void st_bf16x4(__nv_bfloat16* d, float4 v) {
    __nv_bfloat162 p0 = __floats2bfloat162_rn(v.x, v.y);
    __nv_bfloat162 p1 = __floats2bfloat162_rn(v.z, v.w);
    uint2 u;
    u.x = *reinterpret_cast<uint32_t*>(&p0);
    u.y = *reinterpret_cast<uint32_t*>(&p1);
    *reinterpret_cast<uint2*>(d) = u;
}

// ---------------------------------------------------------------------------
// Init: zero h, ring buffer, pad columns of fulb
// ---------------------------------------------------------------------------
__global__ void init_kernel() {
    const int n1 = B_ * H_;
    const int n2 = KK_ * B_ * H_;
    const int n3 = M_ * (FPK_ - F_);
    const int tot = n1 + n2 + n3;
    for (int i = blockIdx.x * blockDim.x + threadIdx.x; i < tot;
         i += gridDim.x * blockDim.x) {
        if (i < n1)           g_h[i] = 0.f;
        else if (i < n1 + n2) g_buf[i - n1] = 0.f;
        else {
            int k = i - n1 - n2;
            int row = k / (FPK_ - F_);
            int c = k % (FPK_ - F_);
            g_fulb[row * FPK_ + F_ + c] = __float2bfloat16(0.f);
        }
    }
}

// ---------------------------------------------------------------------------
// Prep: WA = [Wh | W_hh^T] (1024x4096), WIT = W_ih^T (2048x3072), fp32
// ---------------------------------------------------------------------------
__global__ void prep_kernel(const float* __restrict__ att_W,
                            const float* __restrict__ W_hh,
                            const float* __restrict__ W_ih) {
    const int tot1 = E_ * 4096;
    const int tot2 = 2 * E_ * 3 * H_;
    for (int i = blockIdx.x * blockDim.x + threadIdx.x; i < tot1 + tot2;
         i += gridDim.x * blockDim.x) {
        if (i < tot1) {
            int e = i >> 12;
            int f = i & 4095;
            g_WA[i] = (f < H_) ? att_W[(2 * E_ + e) * E_ + f]
                               : W_hh[(f - H_) * H_ + e];
        } else {
            int k = i - tot1;
            int e = k / (3 * H_);
            int j = k % (3 * H_);
            g_WIT[k] = W_ih[j * (2 * E_) + e];
        }
    }
}

// ---------------------------------------------------------------------------
// Convert lin_W (2058x32000) and att_W[:2048] (2048x1024) to bf16
// ---------------------------------------------------------------------------
__global__ void conv_kernel(const float* __restrict__ lin_W,
                            const float* __restrict__ att_W) {
    const long long n1 = (long long)F_ * NI_ / 4;
    const long long n2 = (long long)2048 * 1024 / 4;
    for (long long i = blockIdx.x * (long long)blockDim.x + threadIdx.x;
         i < n1 + n2; i += (long long)gridDim.x * blockDim.x) {
        if (i < n1) {
            float4 v = *reinterpret_cast<const float4*>(&lin_W[i * 4]);
            st_bf16x4(&g_linWb[i * 4], v);
        } else {
            long long k = i - n1;
            float4 v = *reinterpret_cast<const float4*>(&att_W[k * 4]);
            st_bf16x4(&g_attWb[k * 4], v);
        }
    }
}

// ---------------------------------------------------------------------------
// Gather embeddings into bf16 XUI
// ---------------------------------------------------------------------------
__global__ void gather_kernel(const int* __restrict__ uv,
                              const int* __restrict__ iv,
                              const float* __restrict__ ue,
                              const float* __restrict__ ie) {
    const int tot = M_ * 256;  // float4 chunks of a 1024 row
    for (int i = blockIdx.x * blockDim.x + threadIdx.x; i < tot;
         i += gridDim.x * blockDim.x) {
        int bt = i >> 8;
        int q = (i & 255) * 4;
        float4 u4 = *reinterpret_cast<const float4*>(&ue[(size_t)uv[bt] * E_ + q]);
        float4 i4 = *reinterpret_cast<const float4*>(&ie[(size_t)iv[bt] * E_ + q]);
        st_bf16x4(&g_XUIb[bt * 2048 + q], u4);
        st_bf16x4(&g_XUIb[bt * 2048 + 1024 + q], i4);
    }
}

// ---------------------------------------------------------------------------
// bf16 tensor-core GEMM: C(fp32) = A(bf16,row) @ B(bf16,row KxN) + bias
// Block 128x128x32, 8 warps (2x4), warp tile 64x32, m16n8k16 HMMA,
// cp.async double-buffered, padded conflict-free smem for ldmatrix.
// MODE 0: attpre = XUIb(3200x2048) @ attWb(2048x1024)  -> g_attpre
// MODE 1: logits = fulb(3200x2058 pad 2080) @ linWb(2058x32000) -> Carg
// ---------------------------------------------------------------------------
template <int MODE>
__global__ __launch_bounds__(256)
void mma_gemm_kernel(const float* __restrict__ bias, float* __restrict__ Carg) {
    constexpr int LDA  = (MODE == 0) ? 2048 : FPK_;
    constexpr int LDB  = (MODE == 0) ? 1024 : NI_;
    constexpr int LDC  = LDB;
    constexpr int KD   = (MODE == 0) ? 2048 : F_;    // valid B rows
    constexpr int KPAD = (MODE == 0) ? 2048 : FPK_;  // A stride-padded K
    constexpr int NT   = KPAD / 32;

    const __nv_bfloat16* Ag = (MODE == 0) ? g_XUIb : g_fulb;
    const __nv_bfloat16* Bg = (MODE == 0) ? g_attWb : g_linWb;
    float* C = (MODE == 0) ? g_attpre : Carg;

    __shared__ __nv_bfloat16 As[2][128][40];   // stride 40 -> (5i+c)%8 conflict-free
    __shared__ __nv_bfloat16 Bs[2][32][136];   // stride 136 -> (i+c)%8 conflict-free

    const int tid  = threadIdx.x;
    const int lane = tid & 31;
    const int warp = tid >> 5;
    const int wm = warp >> 2;        // 0..1
    const int wn = warp & 3;         // 0..3
    const int m0 = blockIdx.y * 128;
    const int n0 = blockIdx.x * 128;

    float acc[4][4][4];
#pragma unroll
    for (int a = 0; a < 4; a++)
#pragma unroll
        for (int b = 0; b < 4; b++)
#pragma unroll
            for (int c = 0; c < 4; c++) acc[a][b][c] = 0.f;

#define LOAD_TILE(KT, S)                                                          \
    do {                                                                          \
        int kb = (KT) * 32;                                                       \
        _Pragma("unroll")                                                         \
        for (int i_ = 0; i_ < 2; i_++) {                                          \
            int idx = tid + i_ * 256;                                             \
            int r = idx >> 2, c = idx & 3;                                        \
            uint32_t dst = (uint32_t)__cvta_generic_to_shared(&As[S][r][c * 8]);  \
            const __nv_bfloat16* src = Ag + (size_t)(m0 + r) * LDA + kb + c * 8;  \
            asm volatile("cp.async.cg.shared.global [%0], [%1], 16;\n"            \
                         :: "r"(dst), "l"(src));                                  \
        }                                                                         \
        _Pragma("unroll")                                                         \
        for (int i_ = 0; i_ < 2; i_++) {                                          \
            int idx = tid + i_ * 256;                                             \
            int r = idx >> 4, c = idx & 15;                                       \
            int gr = kb + r;                                                      \
            int grc = (gr < KD) ? gr : (KD - 1);                                  \
            int sz = (gr < KD) ? 16 : 0;                                          \
            uint32_t dst = (uint32_t)__cvta_generic_to_shared(&Bs[S][r][c * 8]);  \
            const __nv_bfloat16* src = Bg + (size_t)grc * LDB + n0 + c * 8;       \
            asm volatile("cp.async.cg.shared.global [%0], [%1], 16, %2;\n"        \
                         :: "r"(dst), "l"(src), "r"(sz));                         \
        }                                                                         \
    } while (0)

    LOAD_TILE(0, 0);
    asm volatile("cp.async.commit_group;\n" ::: "memory");

    for (int kt = 0; kt < NT; kt++) {
        asm volatile("cp.async.wait_group 0;\n" ::: "memory");
        __syncthreads();
        if (kt + 1 < NT) {
            LOAD_TILE(kt + 1, (kt + 1) & 1);
            asm volatile("cp.async.commit_group;\n" ::: "memory");
        }
        const int s = kt & 1;
#pragma unroll
        for (int kh = 0; kh < 2; kh++) {
            uint32_t ra[4][4];
#pragma unroll
            for (int mt = 0; mt < 4; mt++) {
                uint32_t addr = (uint32_t)__cvta_generic_to_shared(
                    &As[s][wm * 64 + mt * 16 + (lane & 15)][kh * 16 + (lane >> 4) * 8]);
                asm volatile(
                    "ldmatrix.sync.aligned.m8n8.x4.shared.b16 {%0,%1,%2,%3}, [%4];\n"
                    : "=r"(ra[mt][0]), "=r"(ra[mt][1]), "=r"(ra[mt][2]), "=r"(ra[mt][3])
                    : "r"(addr));
            }
            uint32_t rb[2][4];
#pragma unroll
            for (int nt2 = 0; nt2 < 2; nt2++) {
                uint32_t addr = (uint32_t)__cvta_generic_to_shared(
                    &Bs[s][kh * 16 + (lane & 15)][wn * 32 + nt2 * 16 + (lane >> 4) * 8]);
                asm volatile(
                    "ldmatrix.sync.aligned.m8n8.x4.trans.shared.b16 {%0,%1,%2,%3}, [%4];\n"
                    : "=r"(rb[nt2][0]), "=r"(rb[nt2][1]), "=r"(rb[nt2][2]), "=r"(rb[nt2][3])
                    : "r"(addr));
            }
#pragma unroll
            for (int mt = 0; mt < 4; mt++)
#pragma unroll
                for (int nt = 0; nt < 4; nt++) {
                    uint32_t b0 = rb[nt >> 1][(nt & 1) * 2];
                    uint32_t b1 = rb[nt >> 1][(nt & 1) * 2 + 1];
                    asm volatile(
                        "mma.sync.aligned.m16n8k16.row.col.f32.bf16.bf16.f32 "
                        "{%0,%1,%2,%3}, {%4,%5,%6,%7}, {%8,%9}, {%0,%1,%2,%3};\n"
                        : "+f"(acc[mt][nt][0]), "+f"(acc[mt][nt][1]),
                          "+f"(acc[mt][nt][2]), "+f"(acc[mt][nt][3])
                        : "r"(ra[mt][0]), "r"(ra[mt][1]), "r"(ra[mt][2]), "r"(ra[mt][3]),
                          "r"(b0), "r"(b1));
                }
        }
    }
#undef LOAD_TILE

#pragma unroll
    for (int mt = 0; mt < 4; mt++) {
        int r0 = m0 + wm * 64 + mt * 16 + (lane >> 2);
#pragma unroll
        for (int nt = 0; nt < 4; nt++) {
            int col = n0 + wn * 32 + nt * 8 + (lane & 3) * 2;
            float b0 = bias[col], b1 = bias[col + 1];
            float2 v0 = make_float2(acc[mt][nt][0] + b0, acc[mt][nt][1] + b1);
            float2 v1 = make_float2(acc[mt][nt][2] + b0, acc[mt][nt][3] + b1);
            *reinterpret_cast<float2*>(&C[(size_t)r0 * LDC + col]) = v0;
            *reinterpret_cast<float2*>(&C[(size_t)(r0 + 8) * LDC + col]) = v1;
        }
    }
}

// ---------------------------------------------------------------------------
// Small-M GEMM (M=64) for the scan, 64x32 tile, BK=32, 4x2 per thread.
// ---------------------------------------------------------------------------
template <int MODE>
__global__ __launch_bounds__(256)
void small_gemm_kernel(int t, const float* __restrict__ bias) {
    constexpr int KD  = (MODE == 0) ? 1024 : 2048;
    constexpr int LDB = (MODE == 0) ? 4096 : 3072;
    const float* A = (MODE == 0) ? g_h : g_x;
    const float* Bm = (MODE == 0) ? g_WA : g_WIT;

    __shared__ float As[32][64];
    __shared__ float Bs[32][32];

    const int tid = threadIdx.x;
    const int n0 = blockIdx.x * 32;
    const int tx = tid & 15;
    const int ty = tid >> 4;

    float acc[4][2] = {{0.f, 0.f}, {0.f, 0.f}, {0.f, 0.f}, {0.f, 0.f}};

    for (int kb = 0; kb < KD; kb += 32) {
#pragma unroll
        for (int i = 0; i < 2; i++) {
            int idx = tid + i * 256;
            int r = idx >> 3;
            int c4 = (idx & 7) * 4;
            float4 v = *reinterpret_cast<const float4*>(&A[r * KD + kb + c4]);
            As[c4 + 0][r] = v.x; As[c4 + 1][r] = v.y;
            As[c4 + 2][r] = v.z; As[c4 + 3][r] = v.w;
        }
        {
            int r = tid >> 3;
            int c4 = (tid & 7) * 4;
            *reinterpret_cast<float4*>(&Bs[r][c4]) =
                *reinterpret_cast<const float4*>(&Bm[(kb + r) * LDB + n0 + c4]);
        }
        __syncthreads();
#pragma unroll
        for (int k = 0; k < 32; k++) {
            float4 a = *reinterpret_cast<const float4*>(&As[k][ty * 4]);
            float2 bv = *reinterpret_cast<const float2*>(&Bs[k][tx * 2]);
            acc[0][0] += a.x * bv.x; acc[0][1] += a.x * bv.y;
            acc[1][0] += a.y * bv.x; acc[1][1] += a.y * bv.y;
            acc[2][0] += a.z * bv.x; acc[2][1] += a.z * bv.y;
            acc[3][0] += a.w * bv.x; acc[3][1] += a.w * bv.y;
        }
        __syncthreads();
    }

#pragma unroll
    for (int i = 0; i < 4; i++) {
        int b = ty * 4 + i;
#pragma unroll
        for (int j = 0; j < 2; j++) {
            int f = n0 + tx * 2 + j;
            float c = acc[i][j];
            if (MODE == 0) {
                if (f < 1024) {
                    int row = b * T_ + t;
                    float a = 1.f / (1.f + __expf(-(g_attpre[row * E_ + f] + c)));
                    float uu = __bfloat162float(g_XUIb[row * 2048 + f]);
                    float ii = __bfloat162float(g_XUIb[row * 2048 + 1024 + f]);
                    g_x[b * 2048 + f]        = a * uu;
                    g_x[b * 2048 + 1024 + f] = (1.f - a) * ii;
                } else {
                    int j2 = f - 1024;
                    g_gh[b * 3072 + j2] = c + bias[j2];
                }
            } else {
                g_gi[b * 3072 + f] = c + bias[f];
            }
        }
    }
}

// ---------------------------------------------------------------------------
// GRU update + sliding-window cov + vertical cov + write fulb row (bf16)
// ---------------------------------------------------------------------------
__global__ __launch_bounds__(256)
void gru_step_kernel(int t,
                     const float* __restrict__ hcov_W,
                     const float* __restrict__ hcov_b,
                     const float* __restrict__ vcov_W,
                     const float* __restrict__ vcov_b) {
    const int b = blockIdx.x;
    const int tid = threadIdx.x;
    __shared__ float hnew[H_];
    __shared__ float cs[WW_];
    __shared__ float rbuf[8];

    const float vw0 = vcov_W[0], vw1 = vcov_W[1], vw2 = vcov_W[2], vw3 = vcov_W[3];
    const float vb = vcov_b[0];
    const int row = b * T_ + t;
    const int slot = t & 3;

    for (int j = tid; j < H_; j += 256) {
        float hold = g_h[b * H_ + j];
        float gir = g_gi[b * 3072 + j];
        float giz = g_gi[b * 3072 + 1024 + j];
        float gin = g_gi[b * 3072 + 2048 + j];
        float ghr = g_gh[b * 3072 + j];
        float ghz = g_gh[b * 3072 + 1024 + j];
        float ghn = g_gh[b * 3072 + 2048 + j];
        float r = 1.f / (1.f + __expf(-(gir + ghr)));
        float z = 1.f / (1.f + __expf(-(giz + ghz)));
        float n = tanhf(gin + r * ghn);
        float hn = (1.f - z) * n + z * hold;
        hnew[j] = hn;
        g_h[b * H_ + j] = hn;
        g_buf[slot * (B_ * H_) + b * H_ + j] = hn;
        float l = 0.f;
        if (t >= KK_ - 1) {
            float q = vw0 * g_buf[((t + 1) & 3) * (B_ * H_) + b * H_ + j]
                    + vw1 * g_buf[((t + 2) & 3) * (B_ * H_) + b * H_ + j]
                    + vw2 * g_buf[((t + 3) & 3) * (B_ * H_) + b * H_ + j]
                    + vw3 * hn + vb;
            l = hn * q;
        }
        g_fulb[row * FPK_ + NN_ + j] = __float2bfloat16(hn);
        g_fulb[row * FPK_ + NN_ + H_ + j] = __float2bfloat16(l);
    }
    __syncthreads();

    float s = 0.f;
    for (int j = tid; j < LOUT_; j += 256) s += hnew[j];
#pragma unroll
    for (int o = 16; o > 0; o >>= 1) s += __shfl_down_sync(0xffffffffu, s, o);
    if ((tid & 31) == 0) rbuf[tid >> 5] = s;
    __syncthreads();
    if (tid == 0) {
        float S = 0.f;
#pragma unroll
        for (int w = 0; w < 8; w++) S += rbuf[w];
        cs[0] = S;
        for (int j = 1; j < WW_; j++)
            cs[j] = cs[j - 1] - hnew[j - 1] + hnew[LOUT_ - 1 + j];
    }
    __syncthreads();
    if (tid < NN_) {
        float v = hcov_b[tid] * (float)LOUT_;
#pragma unroll
        for (int jj = 0; jj < WW_; jj++) v += hcov_W[tid * WW_ + jj] * cs[jj];
        g_fulb[row * FPK_ + tid] = __float2bfloat16(v);
    }
}

// ---------------------------------------------------------------------------
// In-place log-softmax over NI columns, one block per row.
// ---------------------------------------------------------------------------
__global__ __launch_bounds__(512)
void logsoftmax_kernel(float* __restrict__ out) {
    const int row = blockIdx.x;
    float* p = out + (size_t)row * NI_;
    const int tid = threadIdx.x;

    float m = -1e30f, s = 0.f;
    for (int c = tid; c < NI_; c += 512) {
        float v = p[c];
        if (v > m) { s = s * __expf(m - v) + 1.f; m = v; }
        else        s += __expf(v - m);
    }
#pragma unroll
    for (int o = 16; o > 0; o >>= 1) {
        float m2 = __shfl_down_sync(0xffffffffu, m, o);
        float s2 = __shfl_down_sync(0xffffffffu, s, o);
        float M = fmaxf(m, m2);
        s = s * __expf(m - M) + s2 * __expf(m2 - M);
        m = M;
    }
    __shared__ float sm[16], ss[16];
    __shared__ float off;
    if ((tid & 31) == 0) { sm[tid >> 5] = m; ss[tid >> 5] = s; }
    __syncthreads();
    if (tid == 0) {
        float M = sm[0], S = ss[0];
        for (int w = 1; w < 16; w++) {
            float m2 = sm[w], s2 = ss[w];
            float MM = fmaxf(M, m2);
            S = S * __expf(M - MM) + s2 * __expf(m2 - MM);
            M = MM;
        }
        off = M + logf(S);
    }
    __syncthreads();
    float o2 = off;
    for (int c = tid; c < NI_; c += 512) p[c] -= o2;
}

// ---------------------------------------------------------------------------
// Launch
// ---------------------------------------------------------------------------
extern "C" void kernel_launch(void* const* d_in, const int* in_sizes, int n_in,
                              void* d_out, int out_size) {
    (void)in_sizes; (void)n_in; (void)out_size;
    const int*   uv       = (const int*)d_in[0];
    const int*   iv       = (const int*)d_in[1];
    const float* user_emb = (const float*)d_in[2];
    const float* item_emb = (const float*)d_in[3];
    const float* att_W    = (const float*)d_in[4];
    const float* att_b    = (const float*)d_in[5];
    const float* W_ih     = (const float*)d_in[6];
    const float* b_ih     = (const float*)d_in[7];
    const float* W_hh     = (const float*)d_in[8];
    const float* b_hh     = (const float*)d_in[9];
    const float* hcov_W   = (const float*)d_in[10];
    const float* hcov_b   = (const float*)d_in[11];
    const float* vcov_W   = (const float*)d_in[12];
    const float* vcov_b   = (const float*)d_in[13];
    const float* lin_W    = (const float*)d_in[14];
    const float* lin_b    = (const float*)d_in[15];
    float* out = (float*)d_out;

    init_kernel<<<256, 256>>>();
    prep_kernel<<<2048, 256>>>(att_W, W_hh, W_ih);
    conv_kernel<<<4096, 256>>>(lin_W, att_W);
    gather_kernel<<<1024, 256>>>(uv, iv, user_emb, item_emb);

    {   // att_pre = XUIb @ attWb + att_b (tensor cores)
        dim3 grid(E_ / 128, M_ / 128);
        mma_gemm_kernel<0><<<grid, 256>>>(att_b, nullptr);
    }

    for (int t = 0; t < T_; t++) {
        small_gemm_kernel<0><<<4096 / 32, 256>>>(t, b_hh);
        small_gemm_kernel<1><<<3072 / 32, 256>>>(t, b_ih);
        gru_step_kernel<<<B_, 256>>>(t, hcov_W, hcov_b, vcov_W, vcov_b);
    }

    {   // logits = fulb @ linWb + lin_b (tensor cores) -> d_out
        dim3 grid(NI_ / 128, M_ / 128);
        mma_gemm_kernel<1><<<grid, 256>>>(lin_b, out);
    }

    logsoftmax_kernel<<<M_, 512>>>(out);
}

// round 15
// speedup vs baseline: 4.2524x; 1.9741x over previous
#include <cuda_runtime.h>
#include <cuda_bf16.h>
#include <cstdint>

// ---------------------------------------------------------------------------
// Problem constants
// ---------------------------------------------------------------------------
#define B_   64
#define T_   50
#define E_   1024
#define H_   1024
#define NI_  32000
#define KK_  4
#define WW_  32
#define NN_  10
#define LOUT_ 993           // H - W + 1
#define M_   (B_ * T_)      // 3200 rows
#define F_   (NN_ + 2 * H_) // 2058 features into final linear
#define FPK_ 2080           // F_ padded to multiple of 32 (bf16 A stride)

// ---------------------------------------------------------------------------
// Device scratch (static, no runtime allocation)
// ---------------------------------------------------------------------------
__device__ __nv_bfloat16 g_XUIb[M_ * 2048];      // gathered [u|it] in bf16
__device__ float g_attpre[M_ * E_];              // 3200 x 1024 fp32
__device__ __nv_bfloat16 g_WAb[E_ * 4096];       // [Wh | W_hh^T] bf16
__device__ __nv_bfloat16 g_WITb[2 * E_ * 3 * H_];// W_ih^T bf16
__device__ float g_h[B_ * H_];                   // fp32 master hidden state
__device__ __nv_bfloat16 g_hb[B_ * H_];          // bf16 copy for MMA
__device__ float g_gh[B_ * 3 * H_];
__device__ __nv_bfloat16 g_xb[B_ * 2 * E_];      // [att*u,(1-att)*it] bf16
__device__ float g_gi[B_ * 3 * H_];
__device__ float g_buf[KK_ * B_ * H_];
__device__ __nv_bfloat16 g_fulb[M_ * FPK_];      // concat(v,h,l) bf16, padded
__device__ __nv_bfloat16 g_linWb[F_ * NI_];      // lin_W bf16
__device__ __nv_bfloat16 g_attWb[2048 * 1024];   // att_W[:2048] bf16

// ---------------------------------------------------------------------------
// Helpers
// ---------------------------------------------------------------------------
__device__ __forceinline__ void st_bf16x4(__nv_bfloat16* d, float4 v) {
    __nv_bfloat162 p0 = __floats2bfloat162_rn(v.x, v.y);
    __nv_bfloat162 p1 = __floats2bfloat162_rn(v.z, v.w);
    uint2 u;
    u.x = *reinterpret_cast<uint32_t*>(&p0);
    u.y = *reinterpret_cast<uint32_t*>(&p1);
    *reinterpret_cast<uint2*>(d) = u;
}

// ---------------------------------------------------------------------------
// Init: zero h (fp32+bf16), ring buffer, pad columns of fulb
// ---------------------------------------------------------------------------
__global__ void init_kernel() {
    const int n1 = B_ * H_;                 // g_h
    const int n1b = B_ * H_;                // g_hb
    const int n2 = KK_ * B_ * H_;           // g_buf
    const int n3 = M_ * (FPK_ - F_);        // fulb pad
    const int tot = n1 + n1b + n2 + n3;
    for (int i = blockIdx.x * blockDim.x + threadIdx.x; i < tot;
         i += gridDim.x * blockDim.x) {
        if (i < n1)                 g_h[i] = 0.f;
        else if (i < n1 + n1b)      g_hb[i - n1] = __float2bfloat16(0.f);
        else if (i < n1 + n1b + n2) g_buf[i - n1 - n1b] = 0.f;
        else {
            int k = i - n1 - n1b - n2;
            int row = k / (FPK_ - F_);
            int c = k % (FPK_ - F_);
            g_fulb[row * FPK_ + F_ + c] = __float2bfloat16(0.f);
        }
    }
}

// ---------------------------------------------------------------------------
// Prep: WAb = [Wh | W_hh^T] (1024x4096), WITb = W_ih^T (2048x3072), bf16
// ---------------------------------------------------------------------------
__global__ void prep_kernel(const float* __restrict__ att_W,
                            const float* __restrict__ W_hh,
                            const float* __restrict__ W_ih) {
    const int tot1 = E_ * 4096;
    const int tot2 = 2 * E_ * 3 * H_;
    for (int i = blockIdx.x * blockDim.x + threadIdx.x; i < tot1 + tot2;
         i += gridDim.x * blockDim.x) {
        if (i < tot1) {
            int e = i >> 12;
            int f = i & 4095;
            float v = (f < H_) ? att_W[(2 * E_ + e) * E_ + f]
                               : W_hh[(f - H_) * H_ + e];
            g_WAb[i] = __float2bfloat16(v);
        } else {
            int k = i - tot1;
            int e = k / (3 * H_);
            int j = k % (3 * H_);
            g_WITb[k] = __float2bfloat16(W_ih[j * (2 * E_) + e]);
        }
    }
}

// ---------------------------------------------------------------------------
// Convert lin_W (2058x32000) and att_W[:2048] (2048x1024) to bf16
// ---------------------------------------------------------------------------
__global__ void conv_kernel(const float* __restrict__ lin_W,
                            const float* __restrict__ att_W) {
    const long long n1 = (long long)F_ * NI_ / 4;
    const long long n2 = (long long)2048 * 1024 / 4;
    for (long long i = blockIdx.x * (long long)blockDim.x + threadIdx.x;
         i < n1 + n2; i += (long long)gridDim.x * blockDim.x) {
        if (i < n1) {
            float4 v = *reinterpret_cast<const float4*>(&lin_W[i * 4]);
            st_bf16x4(&g_linWb[i * 4], v);
        } else {
            long long k = i - n1;
            float4 v = *reinterpret_cast<const float4*>(&att_W[k * 4]);
            st_bf16x4(&g_attWb[k * 4], v);
        }
    }
}

// ---------------------------------------------------------------------------
// Gather embeddings into bf16 XUI
// ---------------------------------------------------------------------------
__global__ void gather_kernel(const int* __restrict__ uv,
                              const int* __restrict__ iv,
                              const float* __restrict__ ue,
                              const float* __restrict__ ie) {
    const int tot = M_ * 256;
    for (int i = blockIdx.x * blockDim.x + threadIdx.x; i < tot;
         i += gridDim.x * blockDim.x) {
        int bt = i >> 8;
        int q = (i & 255) * 4;
        float4 u4 = *reinterpret_cast<const float4*>(&ue[(size_t)uv[bt] * E_ + q]);
        float4 i4 = *reinterpret_cast<const float4*>(&ie[(size_t)iv[bt] * E_ + q]);
        st_bf16x4(&g_XUIb[bt * 2048 + q], u4);
        st_bf16x4(&g_XUIb[bt * 2048 + 1024 + q], i4);
    }
}

// ---------------------------------------------------------------------------
// Big bf16 tensor-core GEMM. Block 128x128x32, 8 warps, m16n8k16.
// MODE 0: attpre = XUIb(3200x2048) @ attWb(2048x1024)  (grid: x=N,y=M)
// MODE 1: logits = fulb @ linWb + lin_b (grid: x=M tiles, y=N tiles, so a
//         wave of 148 CTAs shares B column tiles -> lin_W streamed once)
// ---------------------------------------------------------------------------
template <int MODE>
__global__ __launch_bounds__(256)
void mma_gemm_kernel(const float* __restrict__ bias, float* __restrict__ Carg) {
    constexpr int LDA  = (MODE == 0) ? 2048 : FPK_;
    constexpr int LDB  = (MODE == 0) ? 1024 : NI_;
    constexpr int LDC  = LDB;
    constexpr int KD   = (MODE == 0) ? 2048 : F_;
    constexpr int KPAD = (MODE == 0) ? 2048 : FPK_;
    constexpr int NT   = KPAD / 32;

    const __nv_bfloat16* Ag = (MODE == 0) ? g_XUIb : g_fulb;
    const __nv_bfloat16* Bg = (MODE == 0) ? g_attWb : g_linWb;
    float* C = (MODE == 0) ? g_attpre : Carg;

    __shared__ __nv_bfloat16 As[2][128][40];
    __shared__ __nv_bfloat16 Bs[2][32][136];

    const int tid  = threadIdx.x;
    const int lane = tid & 31;
    const int warp = tid >> 5;
    const int wm = warp >> 2;
    const int wn = warp & 3;
    const int m0 = (MODE == 0) ? blockIdx.y * 128 : blockIdx.x * 128;
    const int n0 = (MODE == 0) ? blockIdx.x * 128 : blockIdx.y * 128;

    float acc[4][4][4];
#pragma unroll
    for (int a = 0; a < 4; a++)
#pragma unroll
        for (int b = 0; b < 4; b++)
#pragma unroll
            for (int c = 0; c < 4; c++) acc[a][b][c] = 0.f;

#define LOAD_TILE(KT, S)                                                          \
    do {                                                                          \
        int kb = (KT) * 32;                                                       \
        _Pragma("unroll")                                                         \
        for (int i_ = 0; i_ < 2; i_++) {                                          \
            int idx = tid + i_ * 256;                                             \
            int r = idx >> 2, c = idx & 3;                                        \
            uint32_t dst = (uint32_t)__cvta_generic_to_shared(&As[S][r][c * 8]);  \
            const __nv_bfloat16* src = Ag + (size_t)(m0 + r) * LDA + kb + c * 8;  \
            asm volatile("cp.async.cg.shared.global [%0], [%1], 16;\n"            \
                         :: "r"(dst), "l"(src));                                  \
        }                                                                         \
        _Pragma("unroll")                                                         \
        for (int i_ = 0; i_ < 2; i_++) {                                          \
            int idx = tid + i_ * 256;                                             \
            int r = idx >> 4, c = idx & 15;                                       \
            int gr = kb + r;                                                      \
            int grc = (gr < KD) ? gr : (KD - 1);                                  \
            int sz = (gr < KD) ? 16 : 0;                                          \
            uint32_t dst = (uint32_t)__cvta_generic_to_shared(&Bs[S][r][c * 8]);  \
            const __nv_bfloat16* src = Bg + (size_t)grc * LDB + n0 + c * 8;       \
            asm volatile("cp.async.cg.shared.global [%0], [%1], 16, %2;\n"        \
                         :: "r"(dst), "l"(src), "r"(sz));                         \
        }                                                                         \
    } while (0)

    LOAD_TILE(0, 0);
    asm volatile("cp.async.commit_group;\n" ::: "memory");

    for (int kt = 0; kt < NT; kt++) {
        asm volatile("cp.async.wait_group 0;\n" ::: "memory");
        __syncthreads();
        if (kt + 1 < NT) {
            LOAD_TILE(kt + 1, (kt + 1) & 1);
            asm volatile("cp.async.commit_group;\n" ::: "memory");
        }
        const int s = kt & 1;
#pragma unroll
        for (int kh = 0; kh < 2; kh++) {
            uint32_t ra[4][4];
#pragma unroll
            for (int mt = 0; mt < 4; mt++) {
                uint32_t addr = (uint32_t)__cvta_generic_to_shared(
                    &As[s][wm * 64 + mt * 16 + (lane & 15)][kh * 16 + (lane >> 4) * 8]);
                asm volatile(
                    "ldmatrix.sync.aligned.m8n8.x4.shared.b16 {%0,%1,%2,%3}, [%4];\n"
                    : "=r"(ra[mt][0]), "=r"(ra[mt][1]), "=r"(ra[mt][2]), "=r"(ra[mt][3])
                    : "r"(addr));
            }
            uint32_t rb[2][4];
#pragma unroll
            for (int nt2 = 0; nt2 < 2; nt2++) {
                uint32_t addr = (uint32_t)__cvta_generic_to_shared(
                    &Bs[s][kh * 16 + (lane & 15)][wn * 32 + nt2 * 16 + (lane >> 4) * 8]);
                asm volatile(
                    "ldmatrix.sync.aligned.m8n8.x4.trans.shared.b16 {%0,%1,%2,%3}, [%4];\n"
                    : "=r"(rb[nt2][0]), "=r"(rb[nt2][1]), "=r"(rb[nt2][2]), "=r"(rb[nt2][3])
                    : "r"(addr));
            }
#pragma unroll
            for (int mt = 0; mt < 4; mt++)
#pragma unroll
                for (int nt = 0; nt < 4; nt++) {
                    uint32_t b0 = rb[nt >> 1][(nt & 1) * 2];
                    uint32_t b1 = rb[nt >> 1][(nt & 1) * 2 + 1];
                    asm volatile(
                        "mma.sync.aligned.m16n8k16.row.col.f32.bf16.bf16.f32 "
                        "{%0,%1,%2,%3}, {%4,%5,%6,%7}, {%8,%9}, {%0,%1,%2,%3};\n"
                        : "+f"(acc[mt][nt][0]), "+f"(acc[mt][nt][1]),
                          "+f"(acc[mt][nt][2]), "+f"(acc[mt][nt][3])
                        : "r"(ra[mt][0]), "r"(ra[mt][1]), "r"(ra[mt][2]), "r"(ra[mt][3]),
                          "r"(b0), "r"(b1));
                }
        }
    }
#undef LOAD_TILE

#pragma unroll
    for (int mt = 0; mt < 4; mt++) {
        int r0 = m0 + wm * 64 + mt * 16 + (lane >> 2);
#pragma unroll
        for (int nt = 0; nt < 4; nt++) {
            int col = n0 + wn * 32 + nt * 8 + (lane & 3) * 2;
            float b0 = bias[col], b1 = bias[col + 1];
            float2 v0 = make_float2(acc[mt][nt][0] + b0, acc[mt][nt][1] + b1);
            float2 v1 = make_float2(acc[mt][nt][2] + b0, acc[mt][nt][3] + b1);
            *reinterpret_cast<float2*>(&C[(size_t)r0 * LDC + col]) = v0;
            *reinterpret_cast<float2*>(&C[(size_t)(r0 + 8) * LDC + col]) = v1;
        }
    }
}

// ---------------------------------------------------------------------------
// Scan-step bf16 MMA GEMM (M=64). Block 64x32x32, 128 threads (2x2 warps),
// warp tile 32x16, m16n8k16, cp.async double-buffered.
// MODE 0: hb(64x1024) @ WAb(1024x4096); epilogue builds g_xb / g_gh
// MODE 1: xb(64x2048) @ WITb(2048x3072); epilogue g_gi = c + b_ih
// ---------------------------------------------------------------------------
template <int MODE>
__global__ __launch_bounds__(128)
void scan_mma_kernel(int t, const float* __restrict__ bias) {
    constexpr int KD  = (MODE == 0) ? 1024 : 2048;
    constexpr int LDB = (MODE == 0) ? 4096 : 3072;
    constexpr int NT  = KD / 32;
    const __nv_bfloat16* Ag = (MODE == 0) ? g_hb : g_xb;
    const __nv_bfloat16* Bg = (MODE == 0) ? g_WAb : g_WITb;

    __shared__ __nv_bfloat16 As[2][64][40];
    __shared__ __nv_bfloat16 Bs[2][32][40];

    const int tid  = threadIdx.x;
    const int lane = tid & 31;
    const int warp = tid >> 5;
    const int wm = warp >> 1;     // 0..1 (32 rows each)
    const int wn = warp & 1;      // 0..1 (16 cols each)
    const int n0 = blockIdx.x * 32;

    float acc[2][2][4];
#pragma unroll
    for (int a = 0; a < 2; a++)
#pragma unroll
        for (int b = 0; b < 2; b++)
#pragma unroll
            for (int c = 0; c < 4; c++) acc[a][b][c] = 0.f;

#define SLOAD(KT, S)                                                              \
    do {                                                                          \
        int kb = (KT) * 32;                                                       \
        _Pragma("unroll")                                                         \
        for (int i_ = 0; i_ < 2; i_++) {                                          \
            int idx = tid + i_ * 128;                                             \
            int r = idx >> 2, c = idx & 3;                                        \
            uint32_t dst = (uint32_t)__cvta_generic_to_shared(&As[S][r][c * 8]);  \
            const __nv_bfloat16* src = Ag + r * KD + kb + c * 8;                  \
            asm volatile("cp.async.cg.shared.global [%0], [%1], 16;\n"            \
                         :: "r"(dst), "l"(src));                                  \
        }                                                                         \
        {                                                                         \
            int r = tid >> 2, c = tid & 3;                                        \
            uint32_t dst = (uint32_t)__cvta_generic_to_shared(&Bs[S][r][c * 8]);  \
            const __nv_bfloat16* src = Bg + (size_t)(kb + r) * LDB + n0 + c * 8;  \
            asm volatile("cp.async.cg.shared.global [%0], [%1], 16;\n"            \
                         :: "r"(dst), "l"(src));                                  \
        }                                                                         \
    } while (0)

    SLOAD(0, 0);
    asm volatile("cp.async.commit_group;\n" ::: "memory");

    for (int kt = 0; kt < NT; kt++) {
        asm volatile("cp.async.wait_group 0;\n" ::: "memory");
        __syncthreads();
        if (kt + 1 < NT) {
            SLOAD(kt + 1, (kt + 1) & 1);
            asm volatile("cp.async.commit_group;\n" ::: "memory");
        }
        const int s = kt & 1;
#pragma unroll
        for (int kh = 0; kh < 2; kh++) {
            uint32_t ra[2][4];
#pragma unroll
            for (int mt = 0; mt < 2; mt++) {
                uint32_t addr = (uint32_t)__cvta_generic_to_shared(
                    &As[s][wm * 32 + mt * 16 + (lane & 15)][kh * 16 + (lane >> 4) * 8]);
                asm volatile(
                    "ldmatrix.sync.aligned.m8n8.x4.shared.b16 {%0,%1,%2,%3}, [%4];\n"
                    : "=r"(ra[mt][0]), "=r"(ra[mt][1]), "=r"(ra[mt][2]), "=r"(ra[mt][3])
                    : "r"(addr));
            }
            uint32_t rb[4];
            {
                uint32_t addr = (uint32_t)__cvta_generic_to_shared(
                    &Bs[s][kh * 16 + (lane & 15)][wn * 16 + (lane >> 4) * 8]);
                asm volatile(
                    "ldmatrix.sync.aligned.m8n8.x4.trans.shared.b16 {%0,%1,%2,%3}, [%4];\n"
                    : "=r"(rb[0]), "=r"(rb[1]), "=r"(rb[2]), "=r"(rb[3])
                    : "r"(addr));
            }
#pragma unroll
            for (int mt = 0; mt < 2; mt++)
#pragma unroll
                for (int nt = 0; nt < 2; nt++) {
                    asm volatile(
                        "mma.sync.aligned.m16n8k16.row.col.f32.bf16.bf16.f32 "
                        "{%0,%1,%2,%3}, {%4,%5,%6,%7}, {%8,%9}, {%0,%1,%2,%3};\n"
                        : "+f"(acc[mt][nt][0]), "+f"(acc[mt][nt][1]),
                          "+f"(acc[mt][nt][2]), "+f"(acc[mt][nt][3])
                        : "r"(ra[mt][0]), "r"(ra[mt][1]), "r"(ra[mt][2]), "r"(ra[mt][3]),
                          "r"(rb[nt * 2]), "r"(rb[nt * 2 + 1]));
                }
        }
    }
#undef SLOAD

#pragma unroll
    for (int mt = 0; mt < 2; mt++) {
#pragma unroll
        for (int nt = 0; nt < 2; nt++) {
#pragma unroll
            for (int half = 0; half < 2; half++) {
                int b = wm * 32 + mt * 16 + (lane >> 2) + half * 8;
#pragma unroll
                for (int e = 0; e < 2; e++) {
                    int f = n0 + wn * 16 + nt * 8 + (lane & 3) * 2 + e;
                    float c = acc[mt][nt][half * 2 + e];
                    if (MODE == 0) {
                        if (f < 1024) {
                            int row = b * T_ + t;
                            float a = 1.f / (1.f + __expf(-(g_attpre[row * E_ + f] + c)));
                            float uu = __bfloat162float(g_XUIb[row * 2048 + f]);
                            float ii = __bfloat162float(g_XUIb[row * 2048 + 1024 + f]);
                            g_xb[b * 2048 + f]        = __float2bfloat16(a * uu);
                            g_xb[b * 2048 + 1024 + f] = __float2bfloat16((1.f - a) * ii);
                        } else {
                            int j2 = f - 1024;
                            g_gh[b * 3072 + j2] = c + bias[j2];
                        }
                    } else {
                        g_gi[b * 3072 + f] = c + bias[f];
                    }
                }
            }
        }
    }
}

// ---------------------------------------------------------------------------
// GRU update + sliding-window cov + vertical cov + write fulb row (bf16)
// ---------------------------------------------------------------------------
__global__ __launch_bounds__(256)
void gru_step_kernel(int t,
                     const float* __restrict__ hcov_W,
                     const float* __restrict__ hcov_b,
                     const float* __restrict__ vcov_W,
                     const float* __restrict__ vcov_b) {
    const int b = blockIdx.x;
    const int tid = threadIdx.x;
    __shared__ float hnew[H_];
    __shared__ float cs[WW_];
    __shared__ float rbuf[8];

    const float vw0 = vcov_W[0], vw1 = vcov_W[1], vw2 = vcov_W[2], vw3 = vcov_W[3];
    const float vb = vcov_b[0];
    const int row = b * T_ + t;
    const int slot = t & 3;

    for (int j = tid; j < H_; j += 256) {
        float hold = g_h[b * H_ + j];
        float gir = g_gi[b * 3072 + j];
        float giz = g_gi[b * 3072 + 1024 + j];
        float gin = g_gi[b * 3072 + 2048 + j];
        float ghr = g_gh[b * 3072 + j];
        float ghz = g_gh[b * 3072 + 1024 + j];
        float ghn = g_gh[b * 3072 + 2048 + j];
        float r = 1.f / (1.f + __expf(-(gir + ghr)));
        float z = 1.f / (1.f + __expf(-(giz + ghz)));
        float n = tanhf(gin + r * ghn);
        float hn = (1.f - z) * n + z * hold;
        hnew[j] = hn;
        g_h[b * H_ + j] = hn;
        g_hb[b * H_ + j] = __float2bfloat16(hn);
        g_buf[slot * (B_ * H_) + b * H_ + j] = hn;
        float l = 0.f;
        if (t >= KK_ - 1) {
            float q = vw0 * g_buf[((t + 1) & 3) * (B_ * H_) + b * H_ + j]
                    + vw1 * g_buf[((t + 2) & 3) * (B_ * H_) + b * H_ + j]
                    + vw2 * g_buf[((t + 3) & 3) * (B_ * H_) + b * H_ + j]
                    + vw3 * hn + vb;
            l = hn * q;
        }
        g_fulb[row * FPK_ + NN_ + j] = __float2bfloat16(hn);
        g_fulb[row * FPK_ + NN_ + H_ + j] = __float2bfloat16(l);
    }
    __syncthreads();

    float s = 0.f;
    for (int j = tid; j < LOUT_; j += 256) s += hnew[j];
#pragma unroll
    for (int o = 16; o > 0; o >>= 1) s += __shfl_down_sync(0xffffffffu, s, o);
    if ((tid & 31) == 0) rbuf[tid >> 5] = s;
    __syncthreads();
    if (tid == 0) {
        float S = 0.f;
#pragma unroll
        for (int w = 0; w < 8; w++) S += rbuf[w];
        cs[0] = S;
        for (int j = 1; j < WW_; j++)
            cs[j] = cs[j - 1] - hnew[j - 1] + hnew[LOUT_ - 1 + j];
    }
    __syncthreads();
    if (tid < NN_) {
        float v = hcov_b[tid] * (float)LOUT_;
#pragma unroll
        for (int jj = 0; jj < WW_; jj++) v += hcov_W[tid * WW_ + jj] * cs[jj];
        g_fulb[row * FPK_ + tid] = __float2bfloat16(v);
    }
}

// ---------------------------------------------------------------------------
// In-place log-softmax over NI columns, one block per row.
// ---------------------------------------------------------------------------
__global__ __launch_bounds__(512)
void logsoftmax_kernel(float* __restrict__ out) {
    const int row = blockIdx.x;
    float* p = out + (size_t)row * NI_;
    const int tid = threadIdx.x;

    float m = -1e30f, s = 0.f;
    for (int c = tid; c < NI_; c += 512) {
        float v = p[c];
        if (v > m) { s = s * __expf(m - v) + 1.f; m = v; }
        else        s += __expf(v - m);
    }
#pragma unroll
    for (int o = 16; o > 0; o >>= 1) {
        float m2 = __shfl_down_sync(0xffffffffu, m, o);
        float s2 = __shfl_down_sync(0xffffffffu, s, o);
        float M = fmaxf(m, m2);
        s = s * __expf(m - M) + s2 * __expf(m2 - M);
        m = M;
    }
    __shared__ float sm[16], ss[16];
    __shared__ float off;
    if ((tid & 31) == 0) { sm[tid >> 5] = m; ss[tid >> 5] = s; }
    __syncthreads();
    if (tid == 0) {
        float M = sm[0], S = ss[0];
        for (int w = 1; w < 16; w++) {
            float m2 = sm[w], s2 = ss[w];
            float MM = fmaxf(M, m2);
            S = S * __expf(M - MM) + s2 * __expf(m2 - MM);
            M = MM;
        }
        off = M + logf(S);
    }
    __syncthreads();
    float o2 = off;
    for (int c = tid; c < NI_; c += 512) p[c] -= o2;
}

// ---------------------------------------------------------------------------
// Launch
// ---------------------------------------------------------------------------
extern "C" void kernel_launch(void* const* d_in, const int* in_sizes, int n_in,
                              void* d_out, int out_size) {
    (void)in_sizes; (void)n_in; (void)out_size;
    const int*   uv       = (const int*)d_in[0];
    const int*   iv       = (const int*)d_in[1];
    const float* user_emb = (const float*)d_in[2];
    const float* item_emb = (const float*)d_in[3];
    const float* att_W    = (const float*)d_in[4];
    const float* att_b    = (const float*)d_in[5];
    const float* W_ih     = (const float*)d_in[6];
    const float* b_ih     = (const float*)d_in[7];
    const float* W_hh     = (const float*)d_in[8];
    const float* b_hh     = (const float*)d_in[9];
    const float* hcov_W   = (const float*)d_in[10];
    const float* hcov_b   = (const float*)d_in[11];
    const float* vcov_W   = (const float*)d_in[12];
    const float* vcov_b   = (const float*)d_in[13];
    const float* lin_W    = (const float*)d_in[14];
    const float* lin_b    = (const float*)d_in[15];
    float* out = (float*)d_out;

    init_kernel<<<256, 256>>>();
    prep_kernel<<<2048, 256>>>(att_W, W_hh, W_ih);
    conv_kernel<<<4096, 256>>>(lin_W, att_W);
    gather_kernel<<<1024, 256>>>(uv, iv, user_emb, item_emb);

    {   // att_pre = XUIb @ attWb + att_b (tensor cores)
        dim3 grid(E_ / 128, M_ / 128);
        mma_gemm_kernel<0><<<grid, 256>>>(att_b, nullptr);
    }

    for (int t = 0; t < T_; t++) {
        scan_mma_kernel<0><<<4096 / 32, 128>>>(t, b_hh);
        scan_mma_kernel<1><<<3072 / 32, 128>>>(t, b_ih);
        gru_step_kernel<<<B_, 256>>>(t, hcov_W, hcov_b, vcov_W, vcov_b);
    }

    {   // logits = fulb @ linWb + lin_b, M-tiles fastest for L2 reuse of B
        dim3 grid(M_ / 128, NI_ / 128);
        mma_gemm_kernel<1><<<grid, 256>>>(lin_b, out);
    }

    logsoftmax_kernel<<<M_, 512>>>(out);
}

// round 16
// speedup vs baseline: 5.1812x; 1.2184x over previous
#include <cuda_runtime.h>
#include <cuda_bf16.h>
#include <cstdint>

// ---------------------------------------------------------------------------
// Problem constants
// ---------------------------------------------------------------------------
#define B_   64
#define T_   50
#define E_   1024
#define H_   1024
#define NI_  32000
#define KK_  4
#define WW_  32
#define NN_  10
#define LOUT_ 993           // H - W + 1
#define M_   (B_ * T_)      // 3200 rows
#define F_   (NN_ + 2 * H_) // 2058 features into final linear
#define FPK_ 2080           // F_ padded to multiple of 32 (bf16 A stride)
#define BH_  (B_ * H_)      // 65536

// ---------------------------------------------------------------------------
// Device scratch (static, no runtime allocation)
// ---------------------------------------------------------------------------
__device__ __nv_bfloat16 g_XUIb[M_ * 2048];        // gathered [u|it] bf16
__device__ float g_attpre[M_ * E_];                // 3200 x 1024 fp32
__device__ __nv_bfloat16 g_WAb[E_ * 4096];         // [Wh | W_hh^T] bf16
__device__ __nv_bfloat16 g_WITp[2 * E_ * 3 * H_];  // W_ih^T, gate-permuted cols
__device__ float g_hall[(T_ + 1) * BH_];           // full hidden history fp32
__device__ __nv_bfloat16 g_hb[BH_];                // current h bf16 (scan A input)
__device__ float g_ghp[B_ * 3 * H_];               // h@W_hh^T + b_hh, permuted
__device__ __nv_bfloat16 g_xb[B_ * 2 * E_];        // [att*u,(1-att)*it] bf16
__device__ __nv_bfloat16 g_fulb[M_ * FPK_];        // concat(v,h,l) bf16, padded
__device__ __nv_bfloat16 g_linWb[F_ * NI_];        // lin_W bf16
__device__ __nv_bfloat16 g_attWb[2048 * 1024];     // att_W[:2048] bf16

// Permuted column index: q = 48*(j/16) + 16*g + (j%16), j in [0,1024), g in 0..2
// Block nb of scanB handles q in [48*nb, 48*nb+48) = all 3 gates for 16 j's.

// ---------------------------------------------------------------------------
// Helpers
// ---------------------------------------------------------------------------
__device__ __forceinline__ void st_bf16x4(__nv_bfloat16* d, float4 v) {
    __nv_bfloat162 p0 = __floats2bfloat162_rn(v.x, v.y);
    __nv_bfloat162 p1 = __floats2bfloat162_rn(v.z, v.w);
    uint2 u;
    u.x = *reinterpret_cast<uint32_t*>(&p0);
    u.y = *reinterpret_cast<uint32_t*>(&p1);
    *reinterpret_cast<uint2*>(d) = u;
}

// ---------------------------------------------------------------------------
// Init: zero hall slot 0 (h_{-1}), hb, and the pad columns of fulb
// ---------------------------------------------------------------------------
__global__ void init_kernel() {
    const int n1 = BH_;                 // g_hall slot 0
    const int n2 = BH_;                 // g_hb
    const int n3 = M_ * (FPK_ - F_);    // fulb pad
    const int tot = n1 + n2 + n3;
    for (int i = blockIdx.x * blockDim.x + threadIdx.x; i < tot;
         i += gridDim.x * blockDim.x) {
        if (i < n1)           g_hall[i] = 0.f;
        else if (i < n1 + n2) g_hb[i - n1] = __float2bfloat16(0.f);
        else {
            int k = i - n1 - n2;
            int row = k / (FPK_ - F_);
            int c = k % (FPK_ - F_);
            g_fulb[row * FPK_ + F_ + c] = __float2bfloat16(0.f);
        }
    }
}

// ---------------------------------------------------------------------------
// Prep: WAb = [Wh | W_hh^T] (1024x4096), WITp = gate-permuted W_ih^T, bf16
// ---------------------------------------------------------------------------
__global__ void prep_kernel(const float* __restrict__ att_W,
                            const float* __restrict__ W_hh,
                            const float* __restrict__ W_ih) {
    const int tot1 = E_ * 4096;
    const int tot2 = 2 * E_ * 3 * H_;
    for (int i = blockIdx.x * blockDim.x + threadIdx.x; i < tot1 + tot2;
         i += gridDim.x * blockDim.x) {
        if (i < tot1) {
            int e = i >> 12;
            int f = i & 4095;
            float v = (f < H_) ? att_W[(2 * E_ + e) * E_ + f]
                               : W_hh[(f - H_) * H_ + e];
            g_WAb[i] = __float2bfloat16(v);
        } else {
            int k = i - tot1;
            int e = k / 3072;
            int q = k % 3072;
            int j = ((q / 48) << 4) + (q & 15);
            int g = (q % 48) >> 4;
            g_WITp[k] = __float2bfloat16(W_ih[(g * 1024 + j) * 2048 + e]);
        }
    }
}

// ---------------------------------------------------------------------------
// Convert lin_W and att_W[:2048] to bf16
// ---------------------------------------------------------------------------
__global__ void conv_kernel(const float* __restrict__ lin_W,
                            const float* __restrict__ att_W) {
    const long long n1 = (long long)F_ * NI_ / 4;
    const long long n2 = (long long)2048 * 1024 / 4;
    for (long long i = blockIdx.x * (long long)blockDim.x + threadIdx.x;
         i < n1 + n2; i += (long long)gridDim.x * blockDim.x) {
        if (i < n1) {
            float4 v = *reinterpret_cast<const float4*>(&lin_W[i * 4]);
            st_bf16x4(&g_linWb[i * 4], v);
        } else {
            long long k = i - n1;
            float4 v = *reinterpret_cast<const float4*>(&att_W[k * 4]);
            st_bf16x4(&g_attWb[k * 4], v);
        }
    }
}

// ---------------------------------------------------------------------------
// Gather embeddings into bf16 XUI
// ---------------------------------------------------------------------------
__global__ void gather_kernel(const int* __restrict__ uv,
                              const int* __restrict__ iv,
                              const float* __restrict__ ue,
                              const float* __restrict__ ie) {
    const int tot = M_ * 256;
    for (int i = blockIdx.x * blockDim.x + threadIdx.x; i < tot;
         i += gridDim.x * blockDim.x) {
        int bt = i >> 8;
        int q = (i & 255) * 4;
        float4 u4 = *reinterpret_cast<const float4*>(&ue[(size_t)uv[bt] * E_ + q]);
        float4 i4 = *reinterpret_cast<const float4*>(&ie[(size_t)iv[bt] * E_ + q]);
        st_bf16x4(&g_XUIb[bt * 2048 + q], u4);
        st_bf16x4(&g_XUIb[bt * 2048 + 1024 + q], i4);
    }
}

// ---------------------------------------------------------------------------
// Big bf16 tensor-core GEMM. Block 128x128x32, 8 warps, m16n8k16, 2-stage.
// MODE 0: attpre = XUIb @ attWb (grid x=N,y=M)
// MODE 1: logits = fulb @ linWb + lin_b (grid x=M,y=N for L2 reuse of B)
// ---------------------------------------------------------------------------
template <int MODE>
__global__ __launch_bounds__(256)
void mma_gemm_kernel(const float* __restrict__ bias, float* __restrict__ Carg) {
    constexpr int LDA  = (MODE == 0) ? 2048 : FPK_;
    constexpr int LDB  = (MODE == 0) ? 1024 : NI_;
    constexpr int LDC  = LDB;
    constexpr int KD   = (MODE == 0) ? 2048 : F_;
    constexpr int KPAD = (MODE == 0) ? 2048 : FPK_;
    constexpr int NT   = KPAD / 32;

    const __nv_bfloat16* Ag = (MODE == 0) ? g_XUIb : g_fulb;
    const __nv_bfloat16* Bg = (MODE == 0) ? g_attWb : g_linWb;
    float* C = (MODE == 0) ? g_attpre : Carg;

    __shared__ __nv_bfloat16 As[2][128][40];
    __shared__ __nv_bfloat16 Bs[2][32][136];

    const int tid  = threadIdx.x;
    const int lane = tid & 31;
    const int warp = tid >> 5;
    const int wm = warp >> 2;
    const int wn = warp & 3;
    const int m0 = (MODE == 0) ? blockIdx.y * 128 : blockIdx.x * 128;
    const int n0 = (MODE == 0) ? blockIdx.x * 128 : blockIdx.y * 128;

    float acc[4][4][4];
#pragma unroll
    for (int a = 0; a < 4; a++)
#pragma unroll
        for (int b = 0; b < 4; b++)
#pragma unroll
            for (int c = 0; c < 4; c++) acc[a][b][c] = 0.f;

#define LOAD_TILE(KT, S)                                                          \
    do {                                                                          \
        int kb = (KT) * 32;                                                       \
        _Pragma("unroll")                                                         \
        for (int i_ = 0; i_ < 2; i_++) {                                          \
            int idx = tid + i_ * 256;                                             \
            int r = idx >> 2, c = idx & 3;                                        \
            uint32_t dst = (uint32_t)__cvta_generic_to_shared(&As[S][r][c * 8]);  \
            const __nv_bfloat16* src = Ag + (size_t)(m0 + r) * LDA + kb + c * 8;  \
            asm volatile("cp.async.cg.shared.global [%0], [%1], 16;\n"            \
                         :: "r"(dst), "l"(src));                                  \
        }                                                                         \
        _Pragma("unroll")                                                         \
        for (int i_ = 0; i_ < 2; i_++) {                                          \
            int idx = tid + i_ * 256;                                             \
            int r = idx >> 4, c = idx & 15;                                       \
            int gr = kb + r;                                                      \
            int grc = (gr < KD) ? gr : (KD - 1);                                  \
            int sz = (gr < KD) ? 16 : 0;                                          \
            uint32_t dst = (uint32_t)__cvta_generic_to_shared(&Bs[S][r][c * 8]);  \
            const __nv_bfloat16* src = Bg + (size_t)grc * LDB + n0 + c * 8;       \
            asm volatile("cp.async.cg.shared.global [%0], [%1], 16, %2;\n"        \
                         :: "r"(dst), "l"(src), "r"(sz));                         \
        }                                                                         \
    } while (0)

    LOAD_TILE(0, 0);
    asm volatile("cp.async.commit_group;\n" ::: "memory");

    for (int kt = 0; kt < NT; kt++) {
        asm volatile("cp.async.wait_group 0;\n" ::: "memory");
        __syncthreads();
        if (kt + 1 < NT) {
            LOAD_TILE(kt + 1, (kt + 1) & 1);
            asm volatile("cp.async.commit_group;\n" ::: "memory");
        }
        const int s = kt & 1;
#pragma unroll
        for (int kh = 0; kh < 2; kh++) {
            uint32_t ra[4][4];
#pragma unroll
            for (int mt = 0; mt < 4; mt++) {
                uint32_t addr = (uint32_t)__cvta_generic_to_shared(
                    &As[s][wm * 64 + mt * 16 + (lane & 15)][kh * 16 + (lane >> 4) * 8]);
                asm volatile(
                    "ldmatrix.sync.aligned.m8n8.x4.shared.b16 {%0,%1,%2,%3}, [%4];\n"
                    : "=r"(ra[mt][0]), "=r"(ra[mt][1]), "=r"(ra[mt][2]), "=r"(ra[mt][3])
                    : "r"(addr));
            }
            uint32_t rb[2][4];
#pragma unroll
            for (int nt2 = 0; nt2 < 2; nt2++) {
                uint32_t addr = (uint32_t)__cvta_generic_to_shared(
                    &Bs[s][kh * 16 + (lane & 15)][wn * 32 + nt2 * 16 + (lane >> 4) * 8]);
                asm volatile(
                    "ldmatrix.sync.aligned.m8n8.x4.trans.shared.b16 {%0,%1,%2,%3}, [%4];\n"
                    : "=r"(rb[nt2][0]), "=r"(rb[nt2][1]), "=r"(rb[nt2][2]), "=r"(rb[nt2][3])
                    : "r"(addr));
            }
#pragma unroll
            for (int mt = 0; mt < 4; mt++)
#pragma unroll
                for (int nt = 0; nt < 4; nt++) {
                    uint32_t b0 = rb[nt >> 1][(nt & 1) * 2];
                    uint32_t b1 = rb[nt >> 1][(nt & 1) * 2 + 1];
                    asm volatile(
                        "mma.sync.aligned.m16n8k16.row.col.f32.bf16.bf16.f32 "
                        "{%0,%1,%2,%3}, {%4,%5,%6,%7}, {%8,%9}, {%0,%1,%2,%3};\n"
                        : "+f"(acc[mt][nt][0]), "+f"(acc[mt][nt][1]),
                          "+f"(acc[mt][nt][2]), "+f"(acc[mt][nt][3])
                        : "r"(ra[mt][0]), "r"(ra[mt][1]), "r"(ra[mt][2]), "r"(ra[mt][3]),
                          "r"(b0), "r"(b1));
                }
        }
    }
#undef LOAD_TILE

#pragma unroll
    for (int mt = 0; mt < 4; mt++) {
        int r0 = m0 + wm * 64 + mt * 16 + (lane >> 2);
#pragma unroll
        for (int nt = 0; nt < 4; nt++) {
            int col = n0 + wn * 32 + nt * 8 + (lane & 3) * 2;
            float b0 = bias[col], b1 = bias[col + 1];
            float2 v0 = make_float2(acc[mt][nt][0] + b0, acc[mt][nt][1] + b1);
            float2 v1 = make_float2(acc[mt][nt][2] + b0, acc[mt][nt][3] + b1);
            *reinterpret_cast<float2*>(&C[(size_t)r0 * LDC + col]) = v0;
            *reinterpret_cast<float2*>(&C[(size_t)(r0 + 8) * LDC + col]) = v1;
        }
    }
}

// ---------------------------------------------------------------------------
// Scan phase 1: C = hb(64x1024) @ WAb(1024x4096). Block 64x32x32, 128 thr,
// 2x2 warps, warp tile 32x16, 4-stage cp.async pipeline.
// Epilogue: cols<1024 -> att -> g_xb; cols>=1024 -> g_ghp (permuted) + b_hh.
// ---------------------------------------------------------------------------
__global__ __launch_bounds__(128)
void scanA_kernel(int t, const float* __restrict__ bias) {
    constexpr int KD = 1024, LDB = 4096, NT = KD / 32;

    __shared__ __nv_bfloat16 As[4][64][40];
    __shared__ __nv_bfloat16 Bs[4][32][40];

    const int tid  = threadIdx.x;
    const int lane = tid & 31;
    const int warp = tid >> 5;
    const int wm = warp >> 1;
    const int wn = warp & 1;
    const int n0 = blockIdx.x * 32;

    float acc[2][2][4];
#pragma unroll
    for (int a = 0; a < 2; a++)
#pragma unroll
        for (int b = 0; b < 2; b++)
#pragma unroll
            for (int c = 0; c < 4; c++) acc[a][b][c] = 0.f;

#define SLOADA(KT, S)                                                             \
    do {                                                                          \
        int kb = (KT) * 32;                                                       \
        _Pragma("unroll")                                                         \
        for (int i_ = 0; i_ < 2; i_++) {                                          \
            int idx = tid + i_ * 128;                                             \
            int r = idx >> 2, c = idx & 3;                                        \
            uint32_t dst = (uint32_t)__cvta_generic_to_shared(&As[S][r][c * 8]);  \
            const __nv_bfloat16* src = g_hb + r * KD + kb + c * 8;                \
            asm volatile("cp.async.cg.shared.global [%0], [%1], 16;\n"            \
                         :: "r"(dst), "l"(src));                                  \
        }                                                                         \
        {                                                                         \
            int r = tid >> 2, c = tid & 3;                                        \
            uint32_t dst = (uint32_t)__cvta_generic_to_shared(&Bs[S][r][c * 8]);  \
            const __nv_bfloat16* src = g_WAb + (size_t)(kb + r) * LDB + n0 + c * 8;\
            asm volatile("cp.async.cg.shared.global [%0], [%1], 16;\n"            \
                         :: "r"(dst), "l"(src));                                  \
        }                                                                         \
    } while (0)

    SLOADA(0, 0); asm volatile("cp.async.commit_group;\n" ::: "memory");
    SLOADA(1, 1); asm volatile("cp.async.commit_group;\n" ::: "memory");
    SLOADA(2, 2); asm volatile("cp.async.commit_group;\n" ::: "memory");

    for (int kt = 0; kt < NT; kt++) {
        asm volatile("cp.async.wait_group 2;\n" ::: "memory");
        __syncthreads();
        const int s = kt & 3;
#pragma unroll
        for (int kh = 0; kh < 2; kh++) {
            uint32_t ra[2][4];
#pragma unroll
            for (int mt = 0; mt < 2; mt++) {
                uint32_t addr = (uint32_t)__cvta_generic_to_shared(
                    &As[s][wm * 32 + mt * 16 + (lane & 15)][kh * 16 + (lane >> 4) * 8]);
                asm volatile(
                    "ldmatrix.sync.aligned.m8n8.x4.shared.b16 {%0,%1,%2,%3}, [%4];\n"
                    : "=r"(ra[mt][0]), "=r"(ra[mt][1]), "=r"(ra[mt][2]), "=r"(ra[mt][3])
                    : "r"(addr));
            }
            uint32_t rb[4];
            {
                uint32_t addr = (uint32_t)__cvta_generic_to_shared(
                    &Bs[s][kh * 16 + (lane & 15)][wn * 16 + (lane >> 4) * 8]);
                asm volatile(
                    "ldmatrix.sync.aligned.m8n8.x4.trans.shared.b16 {%0,%1,%2,%3}, [%4];\n"
                    : "=r"(rb[0]), "=r"(rb[1]), "=r"(rb[2]), "=r"(rb[3])
                    : "r"(addr));
            }
#pragma unroll
            for (int mt = 0; mt < 2; mt++)
#pragma unroll
                for (int nt = 0; nt < 2; nt++) {
                    asm volatile(
                        "mma.sync.aligned.m16n8k16.row.col.f32.bf16.bf16.f32 "
                        "{%0,%1,%2,%3}, {%4,%5,%6,%7}, {%8,%9}, {%0,%1,%2,%3};\n"
                        : "+f"(acc[mt][nt][0]), "+f"(acc[mt][nt][1]),
                          "+f"(acc[mt][nt][2]), "+f"(acc[mt][nt][3])
                        : "r"(ra[mt][0]), "r"(ra[mt][1]), "r"(ra[mt][2]), "r"(ra[mt][3]),
                          "r"(rb[nt * 2]), "r"(rb[nt * 2 + 1]));
                }
        }
        if (kt + 3 < NT) { SLOADA(kt + 3, (kt + 3) & 3); }
        asm volatile("cp.async.commit_group;\n" ::: "memory");
    }
#undef SLOADA

#pragma unroll
    for (int mt = 0; mt < 2; mt++)
#pragma unroll
        for (int nt = 0; nt < 2; nt++)
#pragma unroll
            for (int half = 0; half < 2; half++) {
                int b = wm * 32 + mt * 16 + (lane >> 2) + half * 8;
#pragma unroll
                for (int e = 0; e < 2; e++) {
                    int f = n0 + wn * 16 + nt * 8 + (lane & 3) * 2 + e;
                    float c = acc[mt][nt][half * 2 + e];
                    if (f < 1024) {
                        int row = b * T_ + t;
                        float a = 1.f / (1.f + __expf(-(g_attpre[row * E_ + f] + c)));
                        float uu = __bfloat162float(g_XUIb[row * 2048 + f]);
                        float ii = __bfloat162float(g_XUIb[row * 2048 + 1024 + f]);
                        g_xb[b * 2048 + f]        = __float2bfloat16(a * uu);
                        g_xb[b * 2048 + 1024 + f] = __float2bfloat16((1.f - a) * ii);
                    } else {
                        int g = (f - 1024) >> 10;
                        int j = (f - 1024) & 1023;
                        int q = ((j >> 4) * 48) + (g << 4) + (j & 15);
                        g_ghp[b * 3072 + q] = c + bias[f - 1024];
                    }
                }
            }
}

// ---------------------------------------------------------------------------
// Scan phase 2 + fused GRU: gi = xb(64x2048) @ WITp(2048x3072), block handles
// all 3 gates for a 16-wide j slice (tile 64x48), 4 warps x 16 rows, 4-stage.
// Epilogue stages gi in smem, then computes hnew -> hall, hb, fulb.
// ---------------------------------------------------------------------------
__global__ __launch_bounds__(128)
void scanB_kernel(int t, const float* __restrict__ b_ih) {
    constexpr int KD = 2048, LDB = 3072, NT = KD / 32;

    __shared__ __nv_bfloat16 As[4][64][40];
    __shared__ __nv_bfloat16 Bs[4][32][56];
    __shared__ float sgi[64][50];

    const int tid  = threadIdx.x;
    const int lane = tid & 31;
    const int warp = tid >> 5;
    const int nb = blockIdx.x;          // j slice [16*nb, 16*nb+16)
    const int n0 = nb * 48;             // permuted column base

    float acc[6][4];
#pragma unroll
    for (int a = 0; a < 6; a++)
#pragma unroll
        for (int c = 0; c < 4; c++) acc[a][c] = 0.f;

#define SLOADB(KT, S)                                                             \
    do {                                                                          \
        int kb = (KT) * 32;                                                       \
        _Pragma("unroll")                                                         \
        for (int i_ = 0; i_ < 2; i_++) {                                          \
            int idx = tid + i_ * 128;                                             \
            int r = idx >> 2, c = idx & 3;                                        \
            uint32_t dst = (uint32_t)__cvta_generic_to_shared(&As[S][r][c * 8]);  \
            const __nv_bfloat16* src = g_xb + r * KD + kb + c * 8;                \
            asm volatile("cp.async.cg.shared.global [%0], [%1], 16;\n"            \
                         :: "r"(dst), "l"(src));                                  \
        }                                                                         \
        _Pragma("unroll")                                                         \
        for (int i_ = 0; i_ < 2; i_++) {                                          \
            int idx = tid + i_ * 128;                                             \
            if (idx < 192) {                                                      \
                int r = idx / 6, c = idx % 6;                                     \
                uint32_t dst = (uint32_t)__cvta_generic_to_shared(&Bs[S][r][c * 8]);\
                const __nv_bfloat16* src =                                        \
                    g_WITp + (size_t)(kb + r) * LDB + n0 + c * 8;                 \
                asm volatile("cp.async.cg.shared.global [%0], [%1], 16;\n"        \
                             :: "r"(dst), "l"(src));                              \
            }                                                                     \
        }                                                                         \
    } while (0)

    SLOADB(0, 0); asm volatile("cp.async.commit_group;\n" ::: "memory");
    SLOADB(1, 1); asm volatile("cp.async.commit_group;\n" ::: "memory");
    SLOADB(2, 2); asm volatile("cp.async.commit_group;\n" ::: "memory");

    for (int kt = 0; kt < NT; kt++) {
        asm volatile("cp.async.wait_group 2;\n" ::: "memory");
        __syncthreads();
        const int s = kt & 3;
#pragma unroll
        for (int kh = 0; kh < 2; kh++) {
            uint32_t ra[4];
            {
                uint32_t addr = (uint32_t)__cvta_generic_to_shared(
                    &As[s][warp * 16 + (lane & 15)][kh * 16 + (lane >> 4) * 8]);
                asm volatile(
                    "ldmatrix.sync.aligned.m8n8.x4.shared.b16 {%0,%1,%2,%3}, [%4];\n"
                    : "=r"(ra[0]), "=r"(ra[1]), "=r"(ra[2]), "=r"(ra[3])
                    : "r"(addr));
            }
            uint32_t rb[3][4];
#pragma unroll
            for (int cb = 0; cb < 3; cb++) {
                uint32_t addr = (uint32_t)__cvta_generic_to_shared(
                    &Bs[s][kh * 16 + (lane & 15)][cb * 16 + (lane >> 4) * 8]);
                asm volatile(
                    "ldmatrix.sync.aligned.m8n8.x4.trans.shared.b16 {%0,%1,%2,%3}, [%4];\n"
                    : "=r"(rb[cb][0]), "=r"(rb[cb][1]), "=r"(rb[cb][2]), "=r"(rb[cb][3])
                    : "r"(addr));
            }
#pragma unroll
            for (int nt = 0; nt < 6; nt++) {
                uint32_t b0 = rb[nt >> 1][(nt & 1) * 2];
                uint32_t b1 = rb[nt >> 1][(nt & 1) * 2 + 1];
                asm volatile(
                    "mma.sync.aligned.m16n8k16.row.col.f32.bf16.bf16.f32 "
                    "{%0,%1,%2,%3}, {%4,%5,%6,%7}, {%8,%9}, {%0,%1,%2,%3};\n"
                    : "+f"(acc[nt][0]), "+f"(acc[nt][1]),
                      "+f"(acc[nt][2]), "+f"(acc[nt][3])
                    : "r"(ra[0]), "r"(ra[1]), "r"(ra[2]), "r"(ra[3]),
                      "r"(b0), "r"(b1));
            }
        }
        if (kt + 3 < NT) { SLOADB(kt + 3, (kt + 3) & 3); }
        asm volatile("cp.async.commit_group;\n" ::: "memory");
    }
#undef SLOADB

    // Stage gi into smem
#pragma unroll
    for (int nt = 0; nt < 6; nt++) {
        int c0 = nt * 8 + (lane & 3) * 2;
        int r0 = warp * 16 + (lane >> 2);
        sgi[r0][c0]     = acc[nt][0];
        sgi[r0][c0 + 1] = acc[nt][1];
        sgi[r0 + 8][c0]     = acc[nt][2];
        sgi[r0 + 8][c0 + 1] = acc[nt][3];
    }
    __syncthreads();

    // Fused GRU update for 64 batches x 16 j's
    const int j0 = nb * 16;
#pragma unroll
    for (int ii = 0; ii < 8; ii++) {
        int e = ii * 128 + tid;
        int b = e >> 4;
        int jl = e & 15;
        int j = j0 + jl;
        int gbase = b * 3072 + n0;
        float gr = sgi[b][jl]      + b_ih[j]        + g_ghp[gbase + jl];
        float gz = sgi[b][16 + jl] + b_ih[1024 + j] + g_ghp[gbase + 16 + jl];
        float gin = sgi[b][32 + jl] + b_ih[2048 + j];
        float ghn = g_ghp[gbase + 32 + jl];
        float hold = g_hall[(size_t)t * BH_ + b * H_ + j];
        float r = 1.f / (1.f + __expf(-gr));
        float z = 1.f / (1.f + __expf(-gz));
        float n = tanhf(gin + r * ghn);
        float hn = (1.f - z) * n + z * hold;
        g_hall[(size_t)(t + 1) * BH_ + b * H_ + j] = hn;
        g_hb[b * H_ + j] = __float2bfloat16(hn);
        g_fulb[(b * T_ + t) * FPK_ + NN_ + j] = __float2bfloat16(hn);
    }
}

// ---------------------------------------------------------------------------
// Post-pass: v (sliding-window cov) and l (vertical cov) for all 3200 rows.
// ---------------------------------------------------------------------------
__global__ __launch_bounds__(256)
void vl_kernel(const float* __restrict__ hcov_W,
               const float* __restrict__ hcov_b,
               const float* __restrict__ vcov_W,
               const float* __restrict__ vcov_b) {
    const int rowid = blockIdx.x;
    const int b = rowid / T_;
    const int t = rowid % T_;
    const int tid = threadIdx.x;
    __shared__ float hnew[H_];
    __shared__ float cs[WW_];
    __shared__ float rbuf[8];

    const float vw0 = vcov_W[0], vw1 = vcov_W[1], vw2 = vcov_W[2], vw3 = vcov_W[3];
    const float vb = vcov_b[0];
    const float* hp = g_hall + (size_t)(t + 1) * BH_ + b * H_;

    for (int j = tid; j < H_; j += 256) {
        float hn = hp[j];
        hnew[j] = hn;
        float l = 0.f;
        if (t >= KK_ - 1) {
            float q = vw0 * g_hall[(size_t)(t - 2) * BH_ + b * H_ + j]
                    + vw1 * g_hall[(size_t)(t - 1) * BH_ + b * H_ + j]
                    + vw2 * g_hall[(size_t)t * BH_ + b * H_ + j]
                    + vw3 * hn + vb;
            l = hn * q;
        }
        g_fulb[rowid * FPK_ + NN_ + H_ + j] = __float2bfloat16(l);
    }
    __syncthreads();

    float s = 0.f;
    for (int j = tid; j < LOUT_; j += 256) s += hnew[j];
#pragma unroll
    for (int o = 16; o > 0; o >>= 1) s += __shfl_down_sync(0xffffffffu, s, o);
    if ((tid & 31) == 0) rbuf[tid >> 5] = s;
    __syncthreads();
    if (tid == 0) {
        float S = 0.f;
#pragma unroll
        for (int w = 0; w < 8; w++) S += rbuf[w];
        cs[0] = S;
        for (int j = 1; j < WW_; j++)
            cs[j] = cs[j - 1] - hnew[j - 1] + hnew[LOUT_ - 1 + j];
    }
    __syncthreads();
    if (tid < NN_) {
        float v = hcov_b[tid] * (float)LOUT_;
#pragma unroll
        for (int jj = 0; jj < WW_; jj++) v += hcov_W[tid * WW_ + jj] * cs[jj];
        g_fulb[rowid * FPK_ + tid] = __float2bfloat16(v);
    }
}

// ---------------------------------------------------------------------------
// In-place log-softmax over NI columns, one block per row.
// ---------------------------------------------------------------------------
__global__ __launch_bounds__(512)
void logsoftmax_kernel(float* __restrict__ out) {
    const int row = blockIdx.x;
    float* p = out + (size_t)row * NI_;
    const int tid = threadIdx.x;

    float m = -1e30f, s = 0.f;
    for (int c = tid; c < NI_; c += 512) {
        float v = p[c];
        if (v > m) { s = s * __expf(m - v) + 1.f; m = v; }
        else        s += __expf(v - m);
    }
#pragma unroll
    for (int o = 16; o > 0; o >>= 1) {
        float m2 = __shfl_down_sync(0xffffffffu, m, o);
        float s2 = __shfl_down_sync(0xffffffffu, s, o);
        float M = fmaxf(m, m2);
        s = s * __expf(m - M) + s2 * __expf(m2 - M);
        m = M;
    }
    __shared__ float sm[16], ss[16];
    __shared__ float off;
    if ((tid & 31) == 0) { sm[tid >> 5] = m; ss[tid >> 5] = s; }
    __syncthreads();
    if (tid == 0) {
        float M = sm[0], S = ss[0];
        for (int w = 1; w < 16; w++) {
            float m2 = sm[w], s2 = ss[w];
            float MM = fmaxf(M, m2);
            S = S * __expf(M - MM) + s2 * __expf(m2 - MM);
            M = MM;
        }
        off = M + logf(S);
    }
    __syncthreads();
    float o2 = off;
    for (int c = tid; c < NI_; c += 512) p[c] -= o2;
}

// ---------------------------------------------------------------------------
// Launch
// ---------------------------------------------------------------------------
extern "C" void kernel_launch(void* const* d_in, const int* in_sizes, int n_in,
                              void* d_out, int out_size) {
    (void)in_sizes; (void)n_in; (void)out_size;
    const int*   uv       = (const int*)d_in[0];
    const int*   iv       = (const int*)d_in[1];
    const float* user_emb = (const float*)d_in[2];
    const float* item_emb = (const float*)d_in[3];
    const float* att_W    = (const float*)d_in[4];
    const float* att_b    = (const float*)d_in[5];
    const float* W_ih     = (const float*)d_in[6];
    const float* b_ih     = (const float*)d_in[7];
    const float* W_hh     = (const float*)d_in[8];
    const float* b_hh     = (const float*)d_in[9];
    const float* hcov_W   = (const float*)d_in[10];
    const float* hcov_b   = (const float*)d_in[11];
    const float* vcov_W   = (const float*)d_in[12];
    const float* vcov_b   = (const float*)d_in[13];
    const float* lin_W    = (const float*)d_in[14];
    const float* lin_b    = (const float*)d_in[15];
    float* out = (float*)d_out;

    init_kernel<<<256, 256>>>();
    prep_kernel<<<2048, 256>>>(att_W, W_hh, W_ih);
    conv_kernel<<<4096, 256>>>(lin_W, att_W);
    gather_kernel<<<1024, 256>>>(uv, iv, user_emb, item_emb);

    {   // att_pre = XUIb @ attWb + att_b
        dim3 grid(E_ / 128, M_ / 128);
        mma_gemm_kernel<0><<<grid, 256>>>(att_b, nullptr);
    }

    for (int t = 0; t < T_; t++) {
        scanA_kernel<<<128, 128>>>(t, b_hh);
        scanB_kernel<<<64, 128>>>(t, b_ih);
    }

    vl_kernel<<<M_, 256>>>(hcov_W, hcov_b, vcov_W, vcov_b);

    {   // logits = fulb @ linWb + lin_b
        dim3 grid(M_ / 128, NI_ / 128);
        mma_gemm_kernel<1><<<grid, 256>>>(lin_b, out);
    }

    logsoftmax_kernel<<<M_, 512>>>(out);
}

// round 17
// speedup vs baseline: 5.2531x; 1.0139x over previous
#include <cuda_runtime.h>
#include <cuda_bf16.h>
#include <cstdint>

// ---------------------------------------------------------------------------
// Problem constants
// ---------------------------------------------------------------------------
#define B_   64
#define T_   50
#define E_   1024
#define H_   1024
#define NI_  32000
#define KK_  4
#define WW_  32
#define NN_  10
#define LOUT_ 993           // H - W + 1
#define M_   (B_ * T_)      // 3200 rows
#define F_   (NN_ + 2 * H_) // 2058 features into final linear
#define FPK_ 2080           // F_ padded to multiple of 32 (bf16 A stride)
#define BH_  (B_ * H_)      // 65536
#define NCTA_ 128           // persistent scan grid

// ---------------------------------------------------------------------------
// Device scratch (static, no runtime allocation)
// ---------------------------------------------------------------------------
__device__ __nv_bfloat16 g_XUIb[M_ * 2048];        // gathered [u|it] bf16
__device__ float g_attpre[M_ * E_];                // 3200 x 1024 fp32
__device__ __nv_bfloat16 g_WAb[E_ * 4096];         // [Wh | W_hh^T] bf16
__device__ __nv_bfloat16 g_WITp[2 * E_ * 3 * H_];  // W_ih^T, gate-permuted cols
__device__ float g_hall[(T_ + 1) * BH_];           // full hidden history fp32
__device__ __nv_bfloat16 g_hb[BH_];                // current h bf16 (scan A input)
__device__ float g_ghp[B_ * 3 * H_];               // h@W_hh^T + b_hh, permuted
__device__ __nv_bfloat16 g_xb[B_ * 2 * E_];        // [att*u,(1-att)*it] bf16
__device__ __nv_bfloat16 g_fulb[M_ * FPK_];        // concat(v,h,l) bf16, padded
__device__ __nv_bfloat16 g_linWb[F_ * NI_];        // lin_W bf16
__device__ __nv_bfloat16 g_attWb[2048 * 1024];     // att_W[:2048] bf16
__device__ unsigned g_bar_count;                   // grid barrier counter

// Permuted column index: q = 48*(j/16) + 16*g + (j%16), j in [0,1024), g in 0..2

// ---------------------------------------------------------------------------
// Helpers
// ---------------------------------------------------------------------------
__device__ __forceinline__ void st_bf16x4(__nv_bfloat16* d, float4 v) {
    __nv_bfloat162 p0 = __floats2bfloat162_rn(v.x, v.y);
    __nv_bfloat162 p1 = __floats2bfloat162_rn(v.z, v.w);
    uint2 u;
    u.x = *reinterpret_cast<uint32_t*>(&p0);
    u.y = *reinterpret_cast<uint32_t*>(&p1);
    *reinterpret_cast<uint2*>(d) = u;
}

// Monotonic-counter grid barrier: all NCTA_ CTAs arrive; target = idx*NCTA_.
__device__ __forceinline__ void gbar(unsigned target) {
    __syncthreads();
    if (threadIdx.x == 0) {
        __threadfence();
        atomicAdd(&g_bar_count, 1u);
        while (*(volatile unsigned*)&g_bar_count < target) { }
        __threadfence();
    }
    __syncthreads();
}

// ---------------------------------------------------------------------------
// Init: zero hall slot 0, hb, fulb pad, barrier counter
// ---------------------------------------------------------------------------
__global__ void init_kernel() {
    if (blockIdx.x == 0 && threadIdx.x == 0) g_bar_count = 0u;
    const int n1 = BH_;
    const int n2 = BH_;
    const int n3 = M_ * (FPK_ - F_);
    const int tot = n1 + n2 + n3;
    for (int i = blockIdx.x * blockDim.x + threadIdx.x; i < tot;
         i += gridDim.x * blockDim.x) {
        if (i < n1)           g_hall[i] = 0.f;
        else if (i < n1 + n2) g_hb[i - n1] = __float2bfloat16(0.f);
        else {
            int k = i - n1 - n2;
            int row = k / (FPK_ - F_);
            int c = k % (FPK_ - F_);
            g_fulb[row * FPK_ + F_ + c] = __float2bfloat16(0.f);
        }
    }
}

// ---------------------------------------------------------------------------
// Prep: WAb = [Wh | W_hh^T] (1024x4096), WITp = gate-permuted W_ih^T, bf16
// ---------------------------------------------------------------------------
__global__ void prep_kernel(const float* __restrict__ att_W,
                            const float* __restrict__ W_hh,
                            const float* __restrict__ W_ih) {
    const int tot1 = E_ * 4096;
    const int tot2 = 2 * E_ * 3 * H_;
    for (int i = blockIdx.x * blockDim.x + threadIdx.x; i < tot1 + tot2;
         i += gridDim.x * blockDim.x) {
        if (i < tot1) {
            int e = i >> 12;
            int f = i & 4095;
            float v = (f < H_) ? att_W[(2 * E_ + e) * E_ + f]
                               : W_hh[(f - H_) * H_ + e];
            g_WAb[i] = __float2bfloat16(v);
        } else {
            int k = i - tot1;
            int e = k / 3072;
            int q = k % 3072;
            int j = ((q / 48) << 4) + (q & 15);
            int g = (q % 48) >> 4;
            g_WITp[k] = __float2bfloat16(W_ih[(g * 1024 + j) * 2048 + e]);
        }
    }
}

// ---------------------------------------------------------------------------
// Convert lin_W and att_W[:2048] to bf16
// ---------------------------------------------------------------------------
__global__ void conv_kernel(const float* __restrict__ lin_W,
                            const float* __restrict__ att_W) {
    const long long n1 = (long long)F_ * NI_ / 4;
    const long long n2 = (long long)2048 * 1024 / 4;
    for (long long i = blockIdx.x * (long long)blockDim.x + threadIdx.x;
         i < n1 + n2; i += (long long)gridDim.x * blockDim.x) {
        if (i < n1) {
            float4 v = *reinterpret_cast<const float4*>(&lin_W[i * 4]);
            st_bf16x4(&g_linWb[i * 4], v);
        } else {
            long long k = i - n1;
            float4 v = *reinterpret_cast<const float4*>(&att_W[k * 4]);
            st_bf16x4(&g_attWb[k * 4], v);
        }
    }
}

// ---------------------------------------------------------------------------
// Gather embeddings into bf16 XUI
// ---------------------------------------------------------------------------
__global__ void gather_kernel(const int* __restrict__ uv,
                              const int* __restrict__ iv,
                              const float* __restrict__ ue,
                              const float* __restrict__ ie) {
    const int tot = M_ * 256;
    for (int i = blockIdx.x * blockDim.x + threadIdx.x; i < tot;
         i += gridDim.x * blockDim.x) {
        int bt = i >> 8;
        int q = (i & 255) * 4;
        float4 u4 = *reinterpret_cast<const float4*>(&ue[(size_t)uv[bt] * E_ + q]);
        float4 i4 = *reinterpret_cast<const float4*>(&ie[(size_t)iv[bt] * E_ + q]);
        st_bf16x4(&g_XUIb[bt * 2048 + q], u4);
        st_bf16x4(&g_XUIb[bt * 2048 + 1024 + q], i4);
    }
}

// ---------------------------------------------------------------------------
// Big bf16 tensor-core GEMM. Block 128x128x32, 8 warps, m16n8k16, 2-stage.
// MODE 0: attpre = XUIb @ attWb (grid x=N,y=M)
// MODE 1: logits = fulb @ linWb + lin_b (grid x=M,y=N for L2 reuse of B)
// ---------------------------------------------------------------------------
template <int MODE>
__global__ __launch_bounds__(256)
void mma_gemm_kernel(const float* __restrict__ bias, float* __restrict__ Carg) {
    constexpr int LDA  = (MODE == 0) ? 2048 : FPK_;
    constexpr int LDB  = (MODE == 0) ? 1024 : NI_;
    constexpr int LDC  = LDB;
    constexpr int KD   = (MODE == 0) ? 2048 : F_;
    constexpr int KPAD = (MODE == 0) ? 2048 : FPK_;
    constexpr int NT   = KPAD / 32;

    const __nv_bfloat16* Ag = (MODE == 0) ? g_XUIb : g_fulb;
    const __nv_bfloat16* Bg = (MODE == 0) ? g_attWb : g_linWb;
    float* C = (MODE == 0) ? g_attpre : Carg;

    __shared__ __nv_bfloat16 As[2][128][40];
    __shared__ __nv_bfloat16 Bs[2][32][136];

    const int tid  = threadIdx.x;
    const int lane = tid & 31;
    const int warp = tid >> 5;
    const int wm = warp >> 2;
    const int wn = warp & 3;
    const int m0 = (MODE == 0) ? blockIdx.y * 128 : blockIdx.x * 128;
    const int n0 = (MODE == 0) ? blockIdx.x * 128 : blockIdx.y * 128;

    float acc[4][4][4];
#pragma unroll
    for (int a = 0; a < 4; a++)
#pragma unroll
        for (int b = 0; b < 4; b++)
#pragma unroll
            for (int c = 0; c < 4; c++) acc[a][b][c] = 0.f;

#define LOAD_TILE(KT, S)                                                          \
    do {                                                                          \
        int kb = (KT) * 32;                                                       \
        _Pragma("unroll")                                                         \
        for (int i_ = 0; i_ < 2; i_++) {                                          \
            int idx = tid + i_ * 256;                                             \
            int r = idx >> 2, c = idx & 3;                                        \
            uint32_t dst = (uint32_t)__cvta_generic_to_shared(&As[S][r][c * 8]);  \
            const __nv_bfloat16* src = Ag + (size_t)(m0 + r) * LDA + kb + c * 8;  \
            asm volatile("cp.async.cg.shared.global [%0], [%1], 16;\n"            \
                         :: "r"(dst), "l"(src));                                  \
        }                                                                         \
        _Pragma("unroll")                                                         \
        for (int i_ = 0; i_ < 2; i_++) {                                          \
            int idx = tid + i_ * 256;                                             \
            int r = idx >> 4, c = idx & 15;                                       \
            int gr = kb + r;                                                      \
            int grc = (gr < KD) ? gr : (KD - 1);                                  \
            int sz = (gr < KD) ? 16 : 0;                                          \
            uint32_t dst = (uint32_t)__cvta_generic_to_shared(&Bs[S][r][c * 8]);  \
            const __nv_bfloat16* src = Bg + (size_t)grc * LDB + n0 + c * 8;       \
            asm volatile("cp.async.cg.shared.global [%0], [%1], 16, %2;\n"        \
                         :: "r"(dst), "l"(src), "r"(sz));                         \
        }                                                                         \
    } while (0)

    LOAD_TILE(0, 0);
    asm volatile("cp.async.commit_group;\n" ::: "memory");

    for (int kt = 0; kt < NT; kt++) {
        asm volatile("cp.async.wait_group 0;\n" ::: "memory");
        __syncthreads();
        if (kt + 1 < NT) {
            LOAD_TILE(kt + 1, (kt + 1) & 1);
            asm volatile("cp.async.commit_group;\n" ::: "memory");
        }
        const int s = kt & 1;
#pragma unroll
        for (int kh = 0; kh < 2; kh++) {
            uint32_t ra[4][4];
#pragma unroll
            for (int mt = 0; mt < 4; mt++) {
                uint32_t addr = (uint32_t)__cvta_generic_to_shared(
                    &As[s][wm * 64 + mt * 16 + (lane & 15)][kh * 16 + (lane >> 4) * 8]);
                asm volatile(
                    "ldmatrix.sync.aligned.m8n8.x4.shared.b16 {%0,%1,%2,%3}, [%4];\n"
                    : "=r"(ra[mt][0]), "=r"(ra[mt][1]), "=r"(ra[mt][2]), "=r"(ra[mt][3])
                    : "r"(addr));
            }
            uint32_t rb[2][4];
#pragma unroll
            for (int nt2 = 0; nt2 < 2; nt2++) {
                uint32_t addr = (uint32_t)__cvta_generic_to_shared(
                    &Bs[s][kh * 16 + (lane & 15)][wn * 32 + nt2 * 16 + (lane >> 4) * 8]);
                asm volatile(
                    "ldmatrix.sync.aligned.m8n8.x4.trans.shared.b16 {%0,%1,%2,%3}, [%4];\n"
                    : "=r"(rb[nt2][0]), "=r"(rb[nt2][1]), "=r"(rb[nt2][2]), "=r"(rb[nt2][3])
                    : "r"(addr));
            }
#pragma unroll
            for (int mt = 0; mt < 4; mt++)
#pragma unroll
                for (int nt = 0; nt < 4; nt++) {
                    uint32_t b0 = rb[nt >> 1][(nt & 1) * 2];
                    uint32_t b1 = rb[nt >> 1][(nt & 1) * 2 + 1];
                    asm volatile(
                        "mma.sync.aligned.m16n8k16.row.col.f32.bf16.bf16.f32 "
                        "{%0,%1,%2,%3}, {%4,%5,%6,%7}, {%8,%9}, {%0,%1,%2,%3};\n"
                        : "+f"(acc[mt][nt][0]), "+f"(acc[mt][nt][1]),
                          "+f"(acc[mt][nt][2]), "+f"(acc[mt][nt][3])
                        : "r"(ra[mt][0]), "r"(ra[mt][1]), "r"(ra[mt][2]), "r"(ra[mt][3]),
                          "r"(b0), "r"(b1));
                }
        }
    }
#undef LOAD_TILE

#pragma unroll
    for (int mt = 0; mt < 4; mt++) {
        int r0 = m0 + wm * 64 + mt * 16 + (lane >> 2);
#pragma unroll
        for (int nt = 0; nt < 4; nt++) {
            int col = n0 + wn * 32 + nt * 8 + (lane & 3) * 2;
            float b0 = bias[col], b1 = bias[col + 1];
            float2 v0 = make_float2(acc[mt][nt][0] + b0, acc[mt][nt][1] + b1);
            float2 v1 = make_float2(acc[mt][nt][2] + b0, acc[mt][nt][3] + b1);
            *reinterpret_cast<float2*>(&C[(size_t)r0 * LDC + col]) = v0;
            *reinterpret_cast<float2*>(&C[(size_t)(r0 + 8) * LDC + col]) = v1;
        }
    }
}

// ---------------------------------------------------------------------------
// Persistent scan: 128 CTAs x 128 threads, all 50 steps inside one kernel.
// Per step: Phase A (all CTAs: h@WA -> xb/ghp), grid barrier,
//           Phase B (CTAs 0-63: xb@WITp + fused GRU -> hall/hb/fulb), barrier.
// Cross-CTA traffic uses cp.async.cg / __ldcg (L1 is not coherent).
// ---------------------------------------------------------------------------
__global__ __launch_bounds__(128, 1)
void scan_persistent_kernel(const float* __restrict__ b_hh,
                            const float* __restrict__ b_ih) {
    __shared__ __nv_bfloat16 As[4][64][40];
    __shared__ __nv_bfloat16 Bs[4][32][56];
    __shared__ float sgi[64][50];

    const int tid  = threadIdx.x;
    const int lane = tid & 31;
    const int warp = tid >> 5;
    const int cta  = blockIdx.x;
    unsigned bt = 0;

    for (int t = 0; t < T_; t++) {
        // ==================== Phase A ====================
        {
            constexpr int KD = 1024, LDB = 4096, NT = KD / 32;
            const int wm = warp >> 1;
            const int wn = warp & 1;
            const int n0 = cta * 32;

            float acc[2][2][4];
#pragma unroll
            for (int a = 0; a < 2; a++)
#pragma unroll
                for (int b = 0; b < 2; b++)
#pragma unroll
                    for (int c = 0; c < 4; c++) acc[a][b][c] = 0.f;

#define SLOADA(KT, S)                                                             \
    do {                                                                          \
        int kb = (KT) * 32;                                                       \
        _Pragma("unroll")                                                         \
        for (int i_ = 0; i_ < 2; i_++) {                                          \
            int idx = tid + i_ * 128;                                             \
            int r = idx >> 2, c = idx & 3;                                        \
            uint32_t dst = (uint32_t)__cvta_generic_to_shared(&As[S][r][c * 8]);  \
            const __nv_bfloat16* src = g_hb + r * KD + kb + c * 8;                \
            asm volatile("cp.async.cg.shared.global [%0], [%1], 16;\n"            \
                         :: "r"(dst), "l"(src));                                  \
        }                                                                         \
        {                                                                         \
            int r = tid >> 2, c = tid & 3;                                        \
            uint32_t dst = (uint32_t)__cvta_generic_to_shared(&Bs[S][r][c * 8]);  \
            const __nv_bfloat16* src = g_WAb + (size_t)(kb + r) * LDB + n0 + c * 8;\
            asm volatile("cp.async.cg.shared.global [%0], [%1], 16;\n"            \
                         :: "r"(dst), "l"(src));                                  \
        }                                                                         \
    } while (0)

            SLOADA(0, 0); asm volatile("cp.async.commit_group;\n" ::: "memory");
            SLOADA(1, 1); asm volatile("cp.async.commit_group;\n" ::: "memory");
            SLOADA(2, 2); asm volatile("cp.async.commit_group;\n" ::: "memory");

            for (int kt = 0; kt < NT; kt++) {
                asm volatile("cp.async.wait_group 2;\n" ::: "memory");
                __syncthreads();
                const int s = kt & 3;
#pragma unroll
                for (int kh = 0; kh < 2; kh++) {
                    uint32_t ra[2][4];
#pragma unroll
                    for (int mt = 0; mt < 2; mt++) {
                        uint32_t addr = (uint32_t)__cvta_generic_to_shared(
                            &As[s][wm * 32 + mt * 16 + (lane & 15)][kh * 16 + (lane >> 4) * 8]);
                        asm volatile(
                            "ldmatrix.sync.aligned.m8n8.x4.shared.b16 {%0,%1,%2,%3}, [%4];\n"
                            : "=r"(ra[mt][0]), "=r"(ra[mt][1]), "=r"(ra[mt][2]), "=r"(ra[mt][3])
                            : "r"(addr));
                    }
                    uint32_t rb[4];
                    {
                        uint32_t addr = (uint32_t)__cvta_generic_to_shared(
                            &Bs[s][kh * 16 + (lane & 15)][wn * 16 + (lane >> 4) * 8]);
                        asm volatile(
                            "ldmatrix.sync.aligned.m8n8.x4.trans.shared.b16 {%0,%1,%2,%3}, [%4];\n"
                            : "=r"(rb[0]), "=r"(rb[1]), "=r"(rb[2]), "=r"(rb[3])
                            : "r"(addr));
                    }
#pragma unroll
                    for (int mt = 0; mt < 2; mt++)
#pragma unroll
                        for (int nt = 0; nt < 2; nt++) {
                            asm volatile(
                                "mma.sync.aligned.m16n8k16.row.col.f32.bf16.bf16.f32 "
                                "{%0,%1,%2,%3}, {%4,%5,%6,%7}, {%8,%9}, {%0,%1,%2,%3};\n"
                                : "+f"(acc[mt][nt][0]), "+f"(acc[mt][nt][1]),
                                  "+f"(acc[mt][nt][2]), "+f"(acc[mt][nt][3])
                                : "r"(ra[mt][0]), "r"(ra[mt][1]), "r"(ra[mt][2]), "r"(ra[mt][3]),
                                  "r"(rb[nt * 2]), "r"(rb[nt * 2 + 1]));
                        }
                }
                if (kt + 3 < NT) { SLOADA(kt + 3, (kt + 3) & 3); }
                asm volatile("cp.async.commit_group;\n" ::: "memory");
            }
#undef SLOADA
            asm volatile("cp.async.wait_group 0;\n" ::: "memory");

#pragma unroll
            for (int mt = 0; mt < 2; mt++)
#pragma unroll
                for (int nt = 0; nt < 2; nt++)
#pragma unroll
                    for (int half = 0; half < 2; half++) {
                        int b = wm * 32 + mt * 16 + (lane >> 2) + half * 8;
#pragma unroll
                        for (int e = 0; e < 2; e++) {
                            int f = n0 + wn * 16 + nt * 8 + (lane & 3) * 2 + e;
                            float c = acc[mt][nt][half * 2 + e];
                            if (f < 1024) {
                                int row = b * T_ + t;
                                float a = 1.f / (1.f + __expf(-(g_attpre[row * E_ + f] + c)));
                                float uu = __bfloat162float(g_XUIb[row * 2048 + f]);
                                float ii = __bfloat162float(g_XUIb[row * 2048 + 1024 + f]);
                                g_xb[b * 2048 + f]        = __float2bfloat16(a * uu);
                                g_xb[b * 2048 + 1024 + f] = __float2bfloat16((1.f - a) * ii);
                            } else {
                                int g = (f - 1024) >> 10;
                                int j = (f - 1024) & 1023;
                                int q = ((j >> 4) * 48) + (g << 4) + (j & 15);
                                g_ghp[b * 3072 + q] = c + b_hh[f - 1024];
                            }
                        }
                    }
        }

        bt += NCTA_; gbar(bt);

        // ==================== Phase B ====================
        if (cta < 64) {
            constexpr int KD = 2048, LDB = 3072, NT = KD / 32;
            const int nb = cta;
            const int n0 = nb * 48;

            float acc[6][4];
#pragma unroll
            for (int a = 0; a < 6; a++)
#pragma unroll
                for (int c = 0; c < 4; c++) acc[a][c] = 0.f;

#define SLOADB(KT, S)                                                             \
    do {                                                                          \
        int kb = (KT) * 32;                                                       \
        _Pragma("unroll")                                                         \
        for (int i_ = 0; i_ < 2; i_++) {                                          \
            int idx = tid + i_ * 128;                                             \
            int r = idx >> 2, c = idx & 3;                                        \
            uint32_t dst = (uint32_t)__cvta_generic_to_shared(&As[S][r][c * 8]);  \
            const __nv_bfloat16* src = g_xb + r * KD + kb + c * 8;                \
            asm volatile("cp.async.cg.shared.global [%0], [%1], 16;\n"            \
                         :: "r"(dst), "l"(src));                                  \
        }                                                                         \
        _Pragma("unroll")                                                         \
        for (int i_ = 0; i_ < 2; i_++) {                                          \
            int idx = tid + i_ * 128;                                             \
            if (idx < 192) {                                                      \
                int r = idx / 6, c = idx % 6;                                     \
                uint32_t dst = (uint32_t)__cvta_generic_to_shared(&Bs[S][r][c * 8]);\
                const __nv_bfloat16* src =                                        \
                    g_WITp + (size_t)(kb + r) * LDB + n0 + c * 8;                 \
                asm volatile("cp.async.cg.shared.global [%0], [%1], 16;\n"        \
                             :: "r"(dst), "l"(src));                              \
            }                                                                     \
        }                                                                         \
    } while (0)

            SLOADB(0, 0); asm volatile("cp.async.commit_group;\n" ::: "memory");
            SLOADB(1, 1); asm volatile("cp.async.commit_group;\n" ::: "memory");
            SLOADB(2, 2); asm volatile("cp.async.commit_group;\n" ::: "memory");

            for (int kt = 0; kt < NT; kt++) {
                asm volatile("cp.async.wait_group 2;\n" ::: "memory");
                __syncthreads();
                const int s = kt & 3;
#pragma unroll
                for (int kh = 0; kh < 2; kh++) {
                    uint32_t ra[4];
                    {
                        uint32_t addr = (uint32_t)__cvta_generic_to_shared(
                            &As[s][warp * 16 + (lane & 15)][kh * 16 + (lane >> 4) * 8]);
                        asm volatile(
                            "ldmatrix.sync.aligned.m8n8.x4.shared.b16 {%0,%1,%2,%3}, [%4];\n"
                            : "=r"(ra[0]), "=r"(ra[1]), "=r"(ra[2]), "=r"(ra[3])
                            : "r"(addr));
                    }
                    uint32_t rb[3][4];
#pragma unroll
                    for (int cb = 0; cb < 3; cb++) {
                        uint32_t addr = (uint32_t)__cvta_generic_to_shared(
                            &Bs[s][kh * 16 + (lane & 15)][cb * 16 + (lane >> 4) * 8]);
                        asm volatile(
                            "ldmatrix.sync.aligned.m8n8.x4.trans.shared.b16 {%0,%1,%2,%3}, [%4];\n"
                            : "=r"(rb[cb][0]), "=r"(rb[cb][1]), "=r"(rb[cb][2]), "=r"(rb[cb][3])
                            : "r"(addr));
                    }
#pragma unroll
                    for (int nt = 0; nt < 6; nt++) {
                        uint32_t b0 = rb[nt >> 1][(nt & 1) * 2];
                        uint32_t b1 = rb[nt >> 1][(nt & 1) * 2 + 1];
                        asm volatile(
                            "mma.sync.aligned.m16n8k16.row.col.f32.bf16.bf16.f32 "
                            "{%0,%1,%2,%3}, {%4,%5,%6,%7}, {%8,%9}, {%0,%1,%2,%3};\n"
                            : "+f"(acc[nt][0]), "+f"(acc[nt][1]),
                              "+f"(acc[nt][2]), "+f"(acc[nt][3])
                            : "r"(ra[0]), "r"(ra[1]), "r"(ra[2]), "r"(ra[3]),
                              "r"(b0), "r"(b1));
                    }
                }
                if (kt + 3 < NT) { SLOADB(kt + 3, (kt + 3) & 3); }
                asm volatile("cp.async.commit_group;\n" ::: "memory");
            }
#undef SLOADB
            asm volatile("cp.async.wait_group 0;\n" ::: "memory");

            // Stage gi into smem
#pragma unroll
            for (int nt = 0; nt < 6; nt++) {
                int c0 = nt * 8 + (lane & 3) * 2;
                int r0 = warp * 16 + (lane >> 2);
                sgi[r0][c0]     = acc[nt][0];
                sgi[r0][c0 + 1] = acc[nt][1];
                sgi[r0 + 8][c0]     = acc[nt][2];
                sgi[r0 + 8][c0 + 1] = acc[nt][3];
            }
            __syncthreads();

            // Fused GRU update: 64 batches x 16 j's
            const int j0 = nb * 16;
#pragma unroll
            for (int ii = 0; ii < 8; ii++) {
                int e = ii * 128 + tid;
                int b = e >> 4;
                int jl = e & 15;
                int j = j0 + jl;
                int gbase = b * 3072 + n0;
                float gr  = sgi[b][jl]      + b_ih[j]        + __ldcg(&g_ghp[gbase + jl]);
                float gz  = sgi[b][16 + jl] + b_ih[1024 + j] + __ldcg(&g_ghp[gbase + 16 + jl]);
                float gin = sgi[b][32 + jl] + b_ih[2048 + j];
                float ghn = __ldcg(&g_ghp[gbase + 32 + jl]);
                float hold = g_hall[(size_t)t * BH_ + b * H_ + j];
                float r = 1.f / (1.f + __expf(-gr));
                float z = 1.f / (1.f + __expf(-gz));
                float n = tanhf(gin + r * ghn);
                float hn = (1.f - z) * n + z * hold;
                g_hall[(size_t)(t + 1) * BH_ + b * H_ + j] = hn;
                g_hb[b * H_ + j] = __float2bfloat16(hn);
                g_fulb[(b * T_ + t) * FPK_ + NN_ + j] = __float2bfloat16(hn);
            }
            __syncthreads();
        }

        bt += NCTA_; gbar(bt);
    }
}

// ---------------------------------------------------------------------------
// Post-pass: v (sliding-window cov) and l (vertical cov) for all 3200 rows.
// ---------------------------------------------------------------------------
__global__ __launch_bounds__(256)
void vl_kernel(const float* __restrict__ hcov_W,
               const float* __restrict__ hcov_b,
               const float* __restrict__ vcov_W,
               const float* __restrict__ vcov_b) {
    const int rowid = blockIdx.x;
    const int b = rowid / T_;
    const int t = rowid % T_;
    const int tid = threadIdx.x;
    __shared__ float hnew[H_];
    __shared__ float cs[WW_];
    __shared__ float rbuf[8];

    const float vw0 = vcov_W[0], vw1 = vcov_W[1], vw2 = vcov_W[2], vw3 = vcov_W[3];
    const float vb = vcov_b[0];
    const float* hp = g_hall + (size_t)(t + 1) * BH_ + b * H_;

    for (int j = tid; j < H_; j += 256) {
        float hn = hp[j];
        hnew[j] = hn;
        float l = 0.f;
        if (t >= KK_ - 1) {
            float q = vw0 * g_hall[(size_t)(t - 2) * BH_ + b * H_ + j]
                    + vw1 * g_hall[(size_t)(t - 1) * BH_ + b * H_ + j]
                    + vw2 * g_hall[(size_t)t * BH_ + b * H_ + j]
                    + vw3 * hn + vb;
            l = hn * q;
        }
        g_fulb[rowid * FPK_ + NN_ + H_ + j] = __float2bfloat16(l);
    }
    __syncthreads();

    float s = 0.f;
    for (int j = tid; j < LOUT_; j += 256) s += hnew[j];
#pragma unroll
    for (int o = 16; o > 0; o >>= 1) s += __shfl_down_sync(0xffffffffu, s, o);
    if ((tid & 31) == 0) rbuf[tid >> 5] = s;
    __syncthreads();
    if (tid == 0) {
        float S = 0.f;
#pragma unroll
        for (int w = 0; w < 8; w++) S += rbuf[w];
        cs[0] = S;
        for (int j = 1; j < WW_; j++)
            cs[j] = cs[j - 1] - hnew[j - 1] + hnew[LOUT_ - 1 + j];
    }
    __syncthreads();
    if (tid < NN_) {
        float v = hcov_b[tid] * (float)LOUT_;
#pragma unroll
        for (int jj = 0; jj < WW_; jj++) v += hcov_W[tid * WW_ + jj] * cs[jj];
        g_fulb[rowid * FPK_ + tid] = __float2bfloat16(v);
    }
}

// ---------------------------------------------------------------------------
// In-place log-softmax over NI columns, one block per row.
// ---------------------------------------------------------------------------
__global__ __launch_bounds__(512)
void logsoftmax_kernel(float* __restrict__ out) {
    const int row = blockIdx.x;
    float* p = out + (size_t)row * NI_;
    const int tid = threadIdx.x;

    float m = -1e30f, s = 0.f;
    for (int c = tid; c < NI_; c += 512) {
        float v = p[c];
        if (v > m) { s = s * __expf(m - v) + 1.f; m = v; }
        else        s += __expf(v - m);
    }
#pragma unroll
    for (int o = 16; o > 0; o >>= 1) {
        float m2 = __shfl_down_sync(0xffffffffu, m, o);
        float s2 = __shfl_down_sync(0xffffffffu, s, o);
        float M = fmaxf(m, m2);
        s = s * __expf(m - M) + s2 * __expf(m2 - M);
        m = M;
    }
    __shared__ float sm[16], ss[16];
    __shared__ float off;
    if ((tid & 31) == 0) { sm[tid >> 5] = m; ss[tid >> 5] = s; }
    __syncthreads();
    if (tid == 0) {
        float M = sm[0], S = ss[0];
        for (int w = 1; w < 16; w++) {
            float m2 = sm[w], s2 = ss[w];
            float MM = fmaxf(M, m2);
            S = S * __expf(M - MM) + s2 * __expf(m2 - MM);
            M = MM;
        }
        off = M + logf(S);
    }
    __syncthreads();
    float o2 = off;
    for (int c = tid; c < NI_; c += 512) p[c] -= o2;
}

// ---------------------------------------------------------------------------
// Launch
// ---------------------------------------------------------------------------
extern "C" void kernel_launch(void* const* d_in, const int* in_sizes, int n_in,
                              void* d_out, int out_size) {
    (void)in_sizes; (void)n_in; (void)out_size;
    const int*   uv       = (const int*)d_in[0];
    const int*   iv       = (const int*)d_in[1];
    const float* user_emb = (const float*)d_in[2];
    const float* item_emb = (const float*)d_in[3];
    const float* att_W    = (const float*)d_in[4];
    const float* att_b    = (const float*)d_in[5];
    const float* W_ih     = (const float*)d_in[6];
    const float* b_ih     = (const float*)d_in[7];
    const float* W_hh     = (const float*)d_in[8];
    const float* b_hh     = (const float*)d_in[9];
    const float* hcov_W   = (const float*)d_in[10];
    const float* hcov_b   = (const float*)d_in[11];
    const float* vcov_W   = (const float*)d_in[12];
    const float* vcov_b   = (const float*)d_in[13];
    const float* lin_W    = (const float*)d_in[14];
    const float* lin_b    = (const float*)d_in[15];
    float* out = (float*)d_out;

    init_kernel<<<256, 256>>>();
    prep_kernel<<<2048, 256>>>(att_W, W_hh, W_ih);
    conv_kernel<<<4096, 256>>>(lin_W, att_W);
    gather_kernel<<<1024, 256>>>(uv, iv, user_emb, item_emb);

    {   // att_pre = XUIb @ attWb + att_b
        dim3 grid(E_ / 128, M_ / 128);
        mma_gemm_kernel<0><<<grid, 256>>>(att_b, nullptr);
    }

    // Entire 50-step recurrence in one persistent kernel
    scan_persistent_kernel<<<NCTA_, 128>>>(b_hh, b_ih);

    vl_kernel<<<M_, 256>>>(hcov_W, hcov_b, vcov_W, vcov_b);

    {   // logits = fulb @ linWb + lin_b
        dim3 grid(M_ / 128, NI_ / 128);
        mma_gemm_kernel<1><<<grid, 256>>>(lin_b, out);
    }

    logsoftmax_kernel<<<M_, 512>>>(out);
}